// round 12
// baseline (speedup 1.0000x reference)
#include <cuda_runtime.h>
#include <cuda_fp16.h>
#include <cstdint>

#define NN 50000
#define NE 640000
#define DIM 128

// ---------------- scratch (device globals: allocation-free rule) ----------------
__device__ float   g_Ax[NN * DIM];           // A output, fp32
__device__ __half  g_Bh[NN * DIM];           // B output, fp16
__device__ __half  g_Dh[NN * DIM];           // D output, fp16
__device__ __half  g_Eh[NN * DIM];           // E output, fp16
__device__ __half2 g_ND[NN * DIM];           // interleaved {num_c, den_c} accumulators
__device__ uint2   g_Wf[5][16 * 16 * 32];    // fragment-packed tf32 weights: A,B,D,E,C
__device__ int     g_hist[NN];               // counting-sort histogram
__device__ int     g_off[NN];                // exclusive offsets (consumed by scatter)
__device__ int     g_psrc[NE];               // src, dst, edge-row in dst-sorted order
__device__ int     g_pdst[NE];
__device__ int     g_prow[NE];
__device__ int     g_i64;

// ---------------- helpers ----------------
__device__ __forceinline__ unsigned f2tf32(float f) {
    unsigned u;
    asm("cvt.rna.tf32.f32 %0, %1;" : "=r"(u) : "f"(f));
    return u;
}

__device__ __forceinline__ void mma_tf32(float c[4], const unsigned a[4],
                                         unsigned b0, unsigned b1) {
    asm volatile(
        "mma.sync.aligned.m16n8k8.row.col.f32.tf32.tf32.f32 "
        "{%0,%1,%2,%3}, {%4,%5,%6,%7}, {%8,%9}, {%0,%1,%2,%3};"
        : "+f"(c[0]), "+f"(c[1]), "+f"(c[2]), "+f"(c[3])
        : "r"(a[0]), "r"(a[1]), "r"(a[2]), "r"(a[3]), "r"(b0), "r"(b1));
}

__device__ __forceinline__ float sigmoidf_(float v) {
    return 1.0f / (1.0f + __expf(-v));
}

__device__ __forceinline__ unsigned pack_h2(float a, float b) {
    __half2 h = __floats2half2_rn(a, b);
    return *reinterpret_cast<unsigned*>(&h);
}

// 64x128x128 GEMM core. sA: [64][132] 32-bit operands in smem (tf32 or raw fp32 bits).
__device__ __forceinline__ void gemm_tile(const unsigned* sA, const uint2* __restrict__ Wf,
                                          float acc[2][4][4], int mBase, int nb,
                                          int r, int c, int lane) {
#pragma unroll 4
    for (int ks = 0; ks < 16; ks++) {
        uint2 b[4];
#pragma unroll
        for (int tj = 0; tj < 4; tj++)
            b[tj] = __ldg(&Wf[(ks * 16 + nb + tj) * 32 + lane]);
        unsigned a[2][4];
#pragma unroll
        for (int ti = 0; ti < 2; ti++) {
            const unsigned* ap = &sA[(mBase + ti * 16 + r) * 132 + ks * 8 + c];
            a[ti][0] = ap[0];
            a[ti][1] = ap[8 * 132];
            a[ti][2] = ap[4];
            a[ti][3] = ap[8 * 132 + 4];
        }
#pragma unroll
        for (int ti = 0; ti < 2; ti++)
#pragma unroll
            for (int tj = 0; tj < 4; tj++)
                mma_tf32(acc[ti][tj], a[ti], b[tj].x, b[tj].y);
    }
}

static const int SMEM_TILE = 64 * 132 * 4;  // 33792 B (node + edge kernels)

// ---------------- kernel 0: zero g_ND + g_hist + detect edge_index dtype ----------------
__global__ void zero_detect_kernel(const unsigned* __restrict__ w) {
    const size_t i = (size_t)blockIdx.x * 256 + threadIdx.x;  // uint4 index over g_ND
    uint4 z = make_uint4(0u, 0u, 0u, 0u);
    ((uint4*)g_ND)[i] = z;
    if (i < NN / 4) ((int4*)g_hist)[i] = make_int4(0, 0, 0, 0);
    if (blockIdx.x == 0 && threadIdx.x < 32) {
        unsigned acc = 0;
        for (int k = threadIdx.x; k < 1024; k += 32) acc |= w[2 * k + 1];
#pragma unroll
        for (int o = 16; o; o >>= 1) acc |= __shfl_xor_sync(0xffffffffu, acc, o);
        if (threadIdx.x == 0) g_i64 = (acc == 0) ? 1 : 0;
    }
}

// ---------------- kernel 0b: histogram over dst ----------------
__global__ void hist_kernel(const void* __restrict__ eidx) {
    const int i = blockIdx.x * 256 + threadIdx.x;
    int dst;
    if (g_i64) dst = (int)((const long long*)eidx)[NE + i];
    else       dst = ((const int*)eidx)[NE + i];
    atomicAdd(&g_hist[dst], 1);
}

// ---------------- kernel 0c: exclusive scan over 50000 bins (single block) ----------------
__global__ void scan_kernel() {
    __shared__ int wsum[32];
    __shared__ int carry;
    const int tid = threadIdx.x, lane = tid & 31, w = tid >> 5;
    if (tid == 0) carry = 0;
    __syncthreads();
    for (int base = 0; base < NN; base += 1024) {
        const int idx = base + tid;
        int v = (idx < NN) ? g_hist[idx] : 0;
        int inc = v;
#pragma unroll
        for (int o = 1; o < 32; o <<= 1) {
            int t = __shfl_up_sync(0xffffffffu, inc, o);
            if (lane >= o) inc += t;
        }
        if (lane == 31) wsum[w] = inc;
        __syncthreads();
        if (w == 0) {
            int s = wsum[lane];
#pragma unroll
            for (int o = 1; o < 32; o <<= 1) {
                int t = __shfl_up_sync(0xffffffffu, s, o);
                if (lane >= o) s += t;
            }
            wsum[lane] = s;  // inclusive warp totals
        }
        __syncthreads();
        const int woff = (w > 0) ? wsum[w - 1] : 0;
        if (idx < NN) g_off[idx] = carry + woff + inc - v;
        __syncthreads();
        if (tid == 0) carry += wsum[31];
        __syncthreads();
    }
}

// ---------------- kernel 0d: scatter edges into dst-sorted order ----------------
__global__ void scatter_kernel(const void* __restrict__ eidx) {
    const int i = blockIdx.x * 256 + threadIdx.x;
    int src, dst;
    if (g_i64) {
        src = (int)((const long long*)eidx)[i];
        dst = (int)((const long long*)eidx)[NE + i];
    } else {
        src = ((const int*)eidx)[i];
        dst = ((const int*)eidx)[NE + i];
    }
    const int pos = atomicAdd(&g_off[dst], 1);
    g_psrc[pos] = src;
    g_pdst[pos] = dst;
    g_prow[pos] = i;
}

// ---------------- kernel 1: pack weights into fragment layout (tf32) ----------------
__global__ void prep_kernel(const float* __restrict__ W0, const float* __restrict__ W1,
                            const float* __restrict__ W2, const float* __restrict__ W3,
                            const float* __restrict__ W4) {
    const float* Ws[5] = {W0, W1, W2, W3, W4};
    const int lane = threadIdx.x;
    const int g = blockIdx.x;      // ks*16+ng
    const int mat = blockIdx.y;
    const int ks = g >> 4, ng = g & 15;
    const int r = lane >> 2, c = lane & 3;
    const float* W = Ws[mat];
    const int n = ng * 8 + r;
    const int k = ks * 8 + c;
    uint2 v;
    v.x = f2tf32(W[n * DIM + k]);
    v.y = f2tf32(W[n * DIM + k + 4]);
    g_Wf[mat][g * 32 + lane] = v;
}

// ---------------- kernel 2: node GEMMs, one j per block ----------------
// j = blockIdx.y: 0->g_Ax fp32, 1->g_Bh half2, 2->g_Dh half2, 3->g_Eh half2
__global__ void __launch_bounds__(256, 4) node_gemm_kernel(
    const float* __restrict__ x,
    const float* __restrict__ b0, const float* __restrict__ b1,
    const float* __restrict__ b2, const float* __restrict__ b3) {
    extern __shared__ unsigned smem[];
    unsigned* sX = smem;  // 64*132 words (tf32 x tile)

    const int tid = threadIdx.x;
    const int m0 = blockIdx.x * 64;
    const int j = blockIdx.y;

    const float* bias = (j == 0) ? b0 : (j == 1) ? b1 : (j == 2) ? b2 : b3;
    const uint2* Wf = g_Wf[j];

    for (int i = tid; i < 64 * 32; i += 256) {
        int row = i >> 5, c4 = (i & 31) << 2;
        float4 v = make_float4(0.f, 0.f, 0.f, 0.f);
        if (m0 + row < NN) v = *(const float4*)&x[(size_t)(m0 + row) * DIM + c4];
        unsigned* p = &sX[row * 132 + c4];
        p[0] = f2tf32(v.x); p[1] = f2tf32(v.y); p[2] = f2tf32(v.z); p[3] = f2tf32(v.w);
    }
    __syncthreads();

    const int lane = tid & 31, wid = tid >> 5;
    const int r = lane >> 2, c = lane & 3;
    const int mBase = (wid & 1) * 32;
    const int nBase = (wid >> 1) * 32;
    const int nb = (wid >> 1) * 4;

    float acc[2][4][4];
#pragma unroll
    for (int tj = 0; tj < 4; tj++) {
        int n0 = nBase + tj * 8 + c * 2;
        float bv0 = __ldg(&bias[n0]), bv1 = __ldg(&bias[n0 + 1]);
#pragma unroll
        for (int ti = 0; ti < 2; ti++) {
            acc[ti][tj][0] = bv0; acc[ti][tj][1] = bv1;
            acc[ti][tj][2] = bv0; acc[ti][tj][3] = bv1;
        }
    }

    gemm_tile(sX, Wf, acc, mBase, nb, r, c, lane);

    __half* outH = (j == 1) ? g_Bh : (j == 2) ? g_Dh : g_Eh;
#pragma unroll
    for (int ti = 0; ti < 2; ti++) {
#pragma unroll
        for (int half_i = 0; half_i < 2; half_i++) {
            const int m = m0 + mBase + ti * 16 + r + half_i * 8;
            if (m >= NN) continue;
#pragma unroll
            for (int tj = 0; tj < 4; tj++) {
                const int n0 = nBase + tj * 8 + c * 2;
                const float v0 = acc[ti][tj][half_i * 2];
                const float v1 = acc[ti][tj][half_i * 2 + 1];
                if (j == 0) {
                    *(float2*)&g_Ax[(size_t)m * DIM + n0] = make_float2(v0, v1);
                } else {
                    *(__half2*)&outH[(size_t)m * DIM + n0] = __floats2half2_rn(v0, v1);
                }
            }
        }
    }
}

// ---------------- kernel 3: fused edge kernel over dst-sorted edges ----------------
// Run-length aggregation: accumulate num/den in fp32 regs across a dst run,
// emit one v4.f16x2 red per run; reload Dx only on run change.
__global__ void __launch_bounds__(256, 4) edge_kernel(
    const float* __restrict__ e,
    const float* __restrict__ Cb,
    const float* __restrict__ beg, const float* __restrict__ beb,
    const float* __restrict__ bem, const float* __restrict__ bev,
    float* __restrict__ e_out) {
    extern __shared__ unsigned smem[];
    __shared__ int s_row[64];
    unsigned* sE = smem;       // raw fp32 e tile; aliased by sO after GEMM
    float* sO = (float*)smem;  // fp32 Ce tile (overwrites sE)

    const int tid = threadIdx.x;
    const int eBase = blockIdx.x * 64;
    const uint2* Wf = g_Wf[4];

    if (tid < 64) s_row[tid] = __ldg(&g_prow[eBase + tid]);
    __syncthreads();

    for (int i = tid; i < 64 * 32; i += 256) {
        int row = i >> 5, c4 = (i & 31) << 2;
        const size_t grow = (size_t)s_row[row];
        float4 v = *(const float4*)&e[grow * DIM + c4];
        float* p = (float*)&sE[row * 132 + c4];
        p[0] = v.x; p[1] = v.y; p[2] = v.z; p[3] = v.w;
    }
    __syncthreads();

    const int lane = tid & 31, wid = tid >> 5;
    const int r = lane >> 2, c = lane & 3;
    const int mBase = (wid & 1) * 32;
    const int nBase = (wid >> 1) * 32;
    const int nb = (wid >> 1) * 4;

    float acc[2][4][4];
#pragma unroll
    for (int tj = 0; tj < 4; tj++) {
        int n0 = nBase + tj * 8 + c * 2;
        float bv0 = __ldg(&Cb[n0]), bv1 = __ldg(&Cb[n0 + 1]);
#pragma unroll
        for (int ti = 0; ti < 2; ti++) {
            acc[ti][tj][0] = bv0; acc[ti][tj][1] = bv1;
            acc[ti][tj][2] = bv0; acc[ti][tj][3] = bv1;
        }
    }

    gemm_tile(sE, Wf, acc, mBase, nb, r, c, lane);

    __syncthreads();  // all sE reads done -> safe to overwrite with sO
#pragma unroll
    for (int ti = 0; ti < 2; ti++) {
        int m = mBase + ti * 16 + r;
#pragma unroll
        for (int tj = 0; tj < 4; tj++) {
            int n0 = nBase + tj * 8 + c * 2;
            sO[m * 132 + n0]           = acc[ti][tj][0];
            sO[m * 132 + n0 + 1]       = acc[ti][tj][1];
            sO[(m + 8) * 132 + n0]     = acc[ti][tj][2];
            sO[(m + 8) * 132 + n0 + 1] = acc[ti][tj][3];
        }
    }
    __syncthreads();

    // ---- epilogue: warp w handles sorted edges w*8..w*8+7, lane owns cols 4*lane..+3
    const int n = lane * 4;
    const float4 gm = *(const float4*)&beg[n];
    const float4 bt = *(const float4*)&beb[n];
    const float4 mn = *(const float4*)&bem[n];
    const float4 vr = *(const float4*)&bev[n];
    const float s0c = gm.x * rsqrtf(vr.x + 1e-5f);
    const float s1c = gm.y * rsqrtf(vr.y + 1e-5f);
    const float s2c = gm.z * rsqrtf(vr.z + 1e-5f);
    const float s3c = gm.w * rsqrtf(vr.w + 1e-5f);
    const float h0c = bt.x - mn.x * s0c;
    const float h1c = bt.y - mn.y * s1c;
    const float h2c = bt.z - mn.z * s2c;
    const float h3c = bt.w - mn.w * s3c;

    int srcs[8], dsts[8], rows[8];
#pragma unroll
    for (int mi = 0; mi < 8; mi++) {
        const int ge = eBase + wid * 8 + mi;
        srcs[mi] = __ldg(&g_psrc[ge]);
        dsts[mi] = __ldg(&g_pdst[ge]);
        rows[mi] = s_row[wid * 8 + mi];
    }

    int curDst = dsts[0];
    uint2 dhu = __ldg((const uint2*)&g_Dh[(size_t)curDst * DIM + n]);
    float2 d01 = __half22float2(*(const __half2*)&dhu.x);
    float2 d23 = __half22float2(*(const __half2*)&dhu.y);
    float aN0 = 0.f, aN1 = 0.f, aN2 = 0.f, aN3 = 0.f;
    float aD0 = 0.f, aD1 = 0.f, aD2 = 0.f, aD3 = 0.f;

#pragma unroll
    for (int mi = 0; mi < 8; mi++) {
        if (dsts[mi] != curDst) {  // uniform across warp (all lanes share dst)
            __half2* ndp = &g_ND[(size_t)curDst * DIM + n];
            asm volatile("red.global.add.noftz.v4.f16x2 [%0], {%1,%2,%3,%4};"
                         :: "l"(ndp), "r"(pack_h2(aN0, aD0)), "r"(pack_h2(aN1, aD1)),
                            "r"(pack_h2(aN2, aD2)), "r"(pack_h2(aN3, aD3))
                         : "memory");
            aN0 = aN1 = aN2 = aN3 = 0.f;
            aD0 = aD1 = aD2 = aD3 = 0.f;
            curDst = dsts[mi];
            dhu = __ldg((const uint2*)&g_Dh[(size_t)curDst * DIM + n]);
            d01 = __half22float2(*(const __half2*)&dhu.x);
            d23 = __half22float2(*(const __half2*)&dhu.y);
        }

        const int m = wid * 8 + mi;
        const int srcI = srcs[mi];

        const uint2 exu = __ldg((const uint2*)&g_Eh[(size_t)srcI * DIM + n]);
        const uint2 bxu = __ldg((const uint2*)&g_Bh[(size_t)srcI * DIM + n]);
        const float2 ex01 = __half22float2(*(const __half2*)&exu.x);
        const float2 ex23 = __half22float2(*(const __half2*)&exu.y);
        const float2 bx01 = __half22float2(*(const __half2*)&bxu.x);
        const float2 bx23 = __half22float2(*(const __half2*)&bxu.y);

        const float4 ce = *(const float4*)&sO[m * 132 + n];

        const float e0 = ce.x + d01.x + ex01.x;
        const float e1 = ce.y + d01.y + ex01.y;
        const float e2 = ce.z + d23.x + ex23.x;
        const float e3 = ce.w + d23.y + ex23.y;

        const float sg0 = sigmoidf_(e0);
        const float sg1 = sigmoidf_(e1);
        const float sg2 = sigmoidf_(e2);
        const float sg3 = sigmoidf_(e3);

        aN0 += sg0 * bx01.x; aD0 += sg0;
        aN1 += sg1 * bx01.y; aD1 += sg1;
        aN2 += sg2 * bx23.x; aD2 += sg2;
        aN3 += sg3 * bx23.y; aD3 += sg3;

        // residual re-read + e_out write at the edge's original row
        const size_t grow = (size_t)rows[mi];
        float4 ev;
        asm volatile("ld.global.cs.v4.f32 {%0,%1,%2,%3}, [%4];"
                     : "=f"(ev.x), "=f"(ev.y), "=f"(ev.z), "=f"(ev.w)
                     : "l"(&e[grow * DIM + n]));
        float4 o;
        o.x = ev.x + fmaxf(0.f, e0 * s0c + h0c);
        o.y = ev.y + fmaxf(0.f, e1 * s1c + h1c);
        o.z = ev.z + fmaxf(0.f, e2 * s2c + h2c);
        o.w = ev.w + fmaxf(0.f, e3 * s3c + h3c);
        asm volatile("st.global.cs.v4.f32 [%0], {%1,%2,%3,%4};"
                     :: "l"(&e_out[grow * DIM + n]),
                        "f"(o.x), "f"(o.y), "f"(o.z), "f"(o.w)
                     : "memory");
    }

    {  // final run flush
        __half2* ndp = &g_ND[(size_t)curDst * DIM + n];
        asm volatile("red.global.add.noftz.v4.f16x2 [%0], {%1,%2,%3,%4};"
                     :: "l"(ndp), "r"(pack_h2(aN0, aD0)), "r"(pack_h2(aN1, aD1)),
                        "r"(pack_h2(aN2, aD2)), "r"(pack_h2(aN3, aD3))
                     : "memory");
    }
}

// ---------------- kernel 4: node update ----------------
__global__ void update_kernel(const float* __restrict__ x,
                              const float* __restrict__ bxg, const float* __restrict__ bxb,
                              const float* __restrict__ bxm, const float* __restrict__ bxv,
                              float* __restrict__ x_out) {
    const size_t i = (size_t)blockIdx.x * 256 + threadIdx.x;  // 4-column index
    const int c4 = ((int)i & 31) << 2;

    const uint4 ndu = ((const uint4*)g_ND)[i];
    const float2 nd0 = __half22float2(*(const __half2*)&ndu.x);  // {num0, den0}
    const float2 nd1 = __half22float2(*(const __half2*)&ndu.y);
    const float2 nd2 = __half22float2(*(const __half2*)&ndu.z);
    const float2 nd3 = __half22float2(*(const __half2*)&ndu.w);

    const float4 ax = ((const float4*)g_Ax)[i];
    const float4 xv = ((const float4*)x)[i];

    const float4 gm = *(const float4*)&bxg[c4];
    const float4 bt = *(const float4*)&bxb[c4];
    const float4 mn = *(const float4*)&bxm[c4];
    const float4 vr = *(const float4*)&bxv[c4];

    const float s0 = gm.x * rsqrtf(vr.x + 1e-5f);
    const float s1 = gm.y * rsqrtf(vr.y + 1e-5f);
    const float s2 = gm.z * rsqrtf(vr.z + 1e-5f);
    const float s3 = gm.w * rsqrtf(vr.w + 1e-5f);
    const float h0 = bt.x - mn.x * s0;
    const float h1 = bt.y - mn.y * s1;
    const float h2 = bt.z - mn.z * s2;
    const float h3 = bt.w - mn.w * s3;

    const float v0 = ax.x + nd0.x / (nd0.y + 1e-6f);
    const float v1 = ax.y + nd1.x / (nd1.y + 1e-6f);
    const float v2 = ax.z + nd2.x / (nd2.y + 1e-6f);
    const float v3 = ax.w + nd3.x / (nd3.y + 1e-6f);

    float4 o;
    o.x = xv.x + fmaxf(0.f, v0 * s0 + h0);
    o.y = xv.y + fmaxf(0.f, v1 * s1 + h1);
    o.z = xv.z + fmaxf(0.f, v2 * s2 + h2);
    o.w = xv.w + fmaxf(0.f, v3 * s3 + h3);
    asm volatile("st.global.cs.v4.f32 [%0], {%1,%2,%3,%4};"
                 :: "l"(&((float4*)x_out)[i]),
                    "f"(o.x), "f"(o.y), "f"(o.z), "f"(o.w)
                 : "memory");
}

// ---------------- launch ----------------
extern "C" void kernel_launch(void* const* d_in, const int* in_sizes, int n_in,
                              void* d_out, int out_size) {
    const float* x  = (const float*)d_in[0];
    const float* e  = (const float*)d_in[1];
    const float* Aw = (const float*)d_in[2];
    const float* Ab = (const float*)d_in[3];
    const float* Bw = (const float*)d_in[4];
    const float* Bb = (const float*)d_in[5];
    const float* Cw = (const float*)d_in[6];
    const float* Cb = (const float*)d_in[7];
    const float* Dw = (const float*)d_in[8];
    const float* Db = (const float*)d_in[9];
    const float* Ew = (const float*)d_in[10];
    const float* Eb = (const float*)d_in[11];
    const float* bxg = (const float*)d_in[12];
    const float* bxb = (const float*)d_in[13];
    const float* bxm = (const float*)d_in[14];
    const float* bxv = (const float*)d_in[15];
    const float* beg = (const float*)d_in[16];
    const float* beb = (const float*)d_in[17];
    const float* bem = (const float*)d_in[18];
    const float* bev = (const float*)d_in[19];
    const void*  eidx = d_in[20];

    float* x_out = (float*)d_out;
    float* e_out = x_out + (size_t)NN * DIM;

    zero_detect_kernel<<<6250, 256>>>((const unsigned*)eidx);
    hist_kernel<<<2500, 256>>>(eidx);
    scan_kernel<<<1, 1024>>>();
    scatter_kernel<<<2500, 256>>>(eidx);
    // weight order: 0:A 1:B 2:D 3:E 4:C
    prep_kernel<<<dim3(256, 5), 32>>>(Aw, Bw, Dw, Ew, Cw);
    node_gemm_kernel<<<dim3(782, 4), 256, SMEM_TILE>>>(x, Ab, Bb, Db, Eb);
    edge_kernel<<<10000, 256, SMEM_TILE>>>(e, Cb, beg, beb, bem, bev, e_out);
    update_kernel<<<6250, 256>>>(x, bxg, bxb, bxm, bxv, x_out);
}

// round 13
// speedup vs baseline: 1.3780x; 1.3780x over previous
#include <cuda_runtime.h>
#include <cuda_fp16.h>
#include <cstdint>

#define NN 50000
#define NE 640000
#define DIM 128

// ---------------- scratch (device globals: allocation-free rule) ----------------
__device__ float  g_Ax[NN * DIM];            // A output, fp32
__device__ __half g_Bh[NN * DIM];            // B output, fp16
__device__ __half g_Dh[NN * DIM];            // D output, fp16
__device__ __half g_Eh[NN * DIM];            // E output, fp16
__device__ __half g_numh[NN * DIM];          // fp16 atomic accumulators
__device__ __half g_denh[NN * DIM];
__device__ uint2  g_Wf[5][16 * 16 * 32];     // fragment-packed tf32 weights: A,B,D,E,C
__device__ int    g_i64;

// ---------------- helpers ----------------
__device__ __forceinline__ unsigned f2tf32(float f) {
    unsigned u;
    asm("cvt.rna.tf32.f32 %0, %1;" : "=r"(u) : "f"(f));
    return u;
}

__device__ __forceinline__ void mma_tf32(float c[4], const unsigned a[4],
                                         unsigned b0, unsigned b1) {
    asm volatile(
        "mma.sync.aligned.m16n8k8.row.col.f32.tf32.tf32.f32 "
        "{%0,%1,%2,%3}, {%4,%5,%6,%7}, {%8,%9}, {%0,%1,%2,%3};"
        : "+f"(c[0]), "+f"(c[1]), "+f"(c[2]), "+f"(c[3])
        : "r"(a[0]), "r"(a[1]), "r"(a[2]), "r"(a[3]), "r"(b0), "r"(b1));
}

__device__ __forceinline__ __half2 tanh_h2(__half2 x) {
    __half2 r;
    asm("tanh.approx.f16x2 %0, %1;"
        : "=r"(*reinterpret_cast<unsigned*>(&r))
        : "r"(*reinterpret_cast<const unsigned*>(&x)));
    return r;
}

__device__ __forceinline__ unsigned h2u(__half2 h) {
    return *reinterpret_cast<unsigned*>(&h);
}

// 64x128x128 GEMM core. sA: [64][132] 32-bit operands in smem (tf32 or raw fp32 bits).
__device__ __forceinline__ void gemm_tile(const unsigned* sA, const uint2* __restrict__ Wf,
                                          float acc[2][4][4], int mBase, int nb,
                                          int r, int c, int lane) {
#pragma unroll 4
    for (int ks = 0; ks < 16; ks++) {
        uint2 b[4];
#pragma unroll
        for (int tj = 0; tj < 4; tj++)
            b[tj] = __ldg(&Wf[(ks * 16 + nb + tj) * 32 + lane]);
        unsigned a[2][4];
#pragma unroll
        for (int ti = 0; ti < 2; ti++) {
            const unsigned* ap = &sA[(mBase + ti * 16 + r) * 132 + ks * 8 + c];
            a[ti][0] = ap[0];
            a[ti][1] = ap[8 * 132];
            a[ti][2] = ap[4];
            a[ti][3] = ap[8 * 132 + 4];
        }
#pragma unroll
        for (int ti = 0; ti < 2; ti++)
#pragma unroll
            for (int tj = 0; tj < 4; tj++)
                mma_tf32(acc[ti][tj], a[ti], b[tj].x, b[tj].y);
    }
}

static const int SMEM_TILE = 64 * 132 * 4;  // 33792 B (node + edge kernels)

// ---------------- kernel 0: zero num/den (fp16) + detect edge_index dtype ----------------
__global__ void zero_detect_kernel(const unsigned* __restrict__ w) {
    const size_t i = (size_t)blockIdx.x * 256 + threadIdx.x;  // float4 index (8 halves)
    float4 z = make_float4(0.f, 0.f, 0.f, 0.f);
    ((float4*)g_numh)[i] = z;
    ((float4*)g_denh)[i] = z;
    if (blockIdx.x == 0 && threadIdx.x < 32) {
        unsigned acc = 0;
        for (int k = threadIdx.x; k < 1024; k += 32) acc |= w[2 * k + 1];
#pragma unroll
        for (int o = 16; o; o >>= 1) acc |= __shfl_xor_sync(0xffffffffu, acc, o);
        if (threadIdx.x == 0) g_i64 = (acc == 0) ? 1 : 0;
    }
}

// ---------------- kernel 1: pack weights into fragment layout (tf32) ----------------
__global__ void prep_kernel(const float* __restrict__ W0, const float* __restrict__ W1,
                            const float* __restrict__ W2, const float* __restrict__ W3,
                            const float* __restrict__ W4) {
    const float* Ws[5] = {W0, W1, W2, W3, W4};
    const int lane = threadIdx.x;
    const int g = blockIdx.x;      // ks*16+ng
    const int mat = blockIdx.y;
    const int ks = g >> 4, ng = g & 15;
    const int r = lane >> 2, c = lane & 3;
    const float* W = Ws[mat];
    const int n = ng * 8 + r;
    const int k = ks * 8 + c;
    uint2 v;
    v.x = f2tf32(W[n * DIM + k]);
    v.y = f2tf32(W[n * DIM + k + 4]);
    g_Wf[mat][g * 32 + lane] = v;
}

// ---------------- kernel 2: node GEMMs, one j per block ----------------
// j = blockIdx.y: 0->g_Ax fp32, 1->g_Bh half2, 2->g_Dh half2, 3->g_Eh half2
__global__ void __launch_bounds__(256, 4) node_gemm_kernel(
    const float* __restrict__ x,
    const float* __restrict__ b0, const float* __restrict__ b1,
    const float* __restrict__ b2, const float* __restrict__ b3) {
    extern __shared__ unsigned smem[];
    unsigned* sX = smem;  // 64*132 words (tf32 x tile)

    const int tid = threadIdx.x;
    const int m0 = blockIdx.x * 64;
    const int j = blockIdx.y;

    const float* bias = (j == 0) ? b0 : (j == 1) ? b1 : (j == 2) ? b2 : b3;
    const uint2* Wf = g_Wf[j];

    for (int i = tid; i < 64 * 32; i += 256) {
        int row = i >> 5, c4 = (i & 31) << 2;
        float4 v = make_float4(0.f, 0.f, 0.f, 0.f);
        if (m0 + row < NN) v = *(const float4*)&x[(size_t)(m0 + row) * DIM + c4];
        unsigned* p = &sX[row * 132 + c4];
        p[0] = f2tf32(v.x); p[1] = f2tf32(v.y); p[2] = f2tf32(v.z); p[3] = f2tf32(v.w);
    }
    __syncthreads();

    const int lane = tid & 31, wid = tid >> 5;
    const int r = lane >> 2, c = lane & 3;
    const int mBase = (wid & 1) * 32;
    const int nBase = (wid >> 1) * 32;
    const int nb = (wid >> 1) * 4;

    float acc[2][4][4];
#pragma unroll
    for (int tj = 0; tj < 4; tj++) {
        int n0 = nBase + tj * 8 + c * 2;
        float bv0 = __ldg(&bias[n0]), bv1 = __ldg(&bias[n0 + 1]);
#pragma unroll
        for (int ti = 0; ti < 2; ti++) {
            acc[ti][tj][0] = bv0; acc[ti][tj][1] = bv1;
            acc[ti][tj][2] = bv0; acc[ti][tj][3] = bv1;
        }
    }

    gemm_tile(sX, Wf, acc, mBase, nb, r, c, lane);

    __half* outH = (j == 1) ? g_Bh : (j == 2) ? g_Dh : g_Eh;
#pragma unroll
    for (int ti = 0; ti < 2; ti++) {
#pragma unroll
        for (int half_i = 0; half_i < 2; half_i++) {
            const int m = m0 + mBase + ti * 16 + r + half_i * 8;
            if (m >= NN) continue;
#pragma unroll
            for (int tj = 0; tj < 4; tj++) {
                const int n0 = nBase + tj * 8 + c * 2;
                const float v0 = acc[ti][tj][half_i * 2];
                const float v1 = acc[ti][tj][half_i * 2 + 1];
                if (j == 0) {
                    *(float2*)&g_Ax[(size_t)m * DIM + n0] = make_float2(v0, v1);
                } else {
                    *(__half2*)&outH[(size_t)m * DIM + n0] = __floats2half2_rn(v0, v1);
                }
            }
        }
    }
}

// ---------------- kernel 3: fused edge kernel, half2 epilogue ----------------
// e staged RAW fp32 in sE (mma truncates). Ce stored to smem as fp16.
// Epilogue: HADD2 sums, tanh.approx.f16x2 sigmoid, HMUL2 gate, v2.f16x2 reds,
// HFMA2/HMAX2 BN+relu, single cvt for fp32 residual add.
__global__ void __launch_bounds__(256, 4) edge_kernel(
    const float* __restrict__ e,
    const float* __restrict__ Cb,
    const void* __restrict__ eidx,
    const float* __restrict__ beg, const float* __restrict__ beb,
    const float* __restrict__ bem, const float* __restrict__ bev,
    float* __restrict__ e_out) {
    extern __shared__ unsigned smem[];
    unsigned* sE = smem;            // raw fp32 e tile; aliased by sOh after GEMM
    __half* sOh = (__half*)smem;    // fp16 Ce tile (overwrites sE)

    const int tid = threadIdx.x;
    const size_t eBase = (size_t)blockIdx.x * 64;
    const uint2* Wf = g_Wf[4];

    for (int i = tid; i < 64 * 32; i += 256) {
        int row = i >> 5, c4 = (i & 31) << 2;
        float4 v = *(const float4*)&e[(eBase + row) * DIM + c4];
        float* p = (float*)&sE[row * 132 + c4];
        p[0] = v.x; p[1] = v.y; p[2] = v.z; p[3] = v.w;
    }
    __syncthreads();

    const int lane = tid & 31, wid = tid >> 5;
    const int r = lane >> 2, c = lane & 3;
    const int mBase = (wid & 1) * 32;
    const int nBase = (wid >> 1) * 32;
    const int nb = (wid >> 1) * 4;

    float acc[2][4][4];
#pragma unroll
    for (int tj = 0; tj < 4; tj++) {
        int n0 = nBase + tj * 8 + c * 2;
        float bv0 = __ldg(&Cb[n0]), bv1 = __ldg(&Cb[n0 + 1]);
#pragma unroll
        for (int ti = 0; ti < 2; ti++) {
            acc[ti][tj][0] = bv0; acc[ti][tj][1] = bv1;
            acc[ti][tj][2] = bv0; acc[ti][tj][3] = bv1;
        }
    }

    gemm_tile(sE, Wf, acc, mBase, nb, r, c, lane);

    __syncthreads();  // all sE reads done -> safe to overwrite with sOh
#pragma unroll
    for (int ti = 0; ti < 2; ti++) {
        int m = mBase + ti * 16 + r;
#pragma unroll
        for (int tj = 0; tj < 4; tj++) {
            int n0 = nBase + tj * 8 + c * 2;
            *(__half2*)&sOh[m * 132 + n0] =
                __floats2half2_rn(acc[ti][tj][0], acc[ti][tj][1]);
            *(__half2*)&sOh[(m + 8) * 132 + n0] =
                __floats2half2_rn(acc[ti][tj][2], acc[ti][tj][3]);
        }
    }
    __syncthreads();

    // ---- epilogue: warp w handles edges w*8..w*8+7, lane owns cols 4*lane..+3
    const int n = lane * 4;
    const float4 gm = *(const float4*)&beg[n];
    const float4 bt = *(const float4*)&beb[n];
    const float4 mn = *(const float4*)&bem[n];
    const float4 vr = *(const float4*)&bev[n];
    const float s0c = gm.x * rsqrtf(vr.x + 1e-5f);
    const float s1c = gm.y * rsqrtf(vr.y + 1e-5f);
    const float s2c = gm.z * rsqrtf(vr.z + 1e-5f);
    const float s3c = gm.w * rsqrtf(vr.w + 1e-5f);
    // BN constants as half2
    const __half2 sH01 = __floats2half2_rn(s0c, s1c);
    const __half2 sH23 = __floats2half2_rn(s2c, s3c);
    const __half2 hH01 = __floats2half2_rn(bt.x - mn.x * s0c, bt.y - mn.y * s1c);
    const __half2 hH23 = __floats2half2_rn(bt.z - mn.z * s2c, bt.w - mn.w * s3c);
    const __half2 halfC = __floats2half2_rn(0.5f, 0.5f);
    const __half2 zeroC = __floats2half2_rn(0.f, 0.f);

    const int flag = g_i64;
    const long long* i64p = (const long long*)eidx;
    const int* i32p = (const int*)eidx;

    int srcs[8], dsts[8];
    if (flag) {
#pragma unroll
        for (int mi = 0; mi < 8; mi++) {
            const size_t ge = eBase + wid * 8 + mi;
            srcs[mi] = (int)__ldg(&i64p[ge]);
            dsts[mi] = (int)__ldg(&i64p[NE + ge]);
        }
    } else {
#pragma unroll
        for (int mi = 0; mi < 8; mi++) {
            const size_t ge = eBase + wid * 8 + mi;
            srcs[mi] = __ldg(&i32p[ge]);
            dsts[mi] = __ldg(&i32p[NE + ge]);
        }
    }

#pragma unroll
    for (int mi = 0; mi < 8; mi++) {
        const int m = wid * 8 + mi;
        const size_t ge = eBase + m;
        const int srcI = srcs[mi], dstI = dsts[mi];

        const uint2 exu = __ldg((const uint2*)&g_Eh[(size_t)srcI * DIM + n]);
        const uint2 bxu = __ldg((const uint2*)&g_Bh[(size_t)srcI * DIM + n]);
        const uint2 dhu = __ldg((const uint2*)&g_Dh[(size_t)dstI * DIM + n]);
        const uint2 ceu = *(const uint2*)&sOh[m * 132 + n];

        const __half2 ex01 = *(const __half2*)&exu.x;
        const __half2 ex23 = *(const __half2*)&exu.y;
        const __half2 bx01 = *(const __half2*)&bxu.x;
        const __half2 bx23 = *(const __half2*)&bxu.y;
        const __half2 d01  = *(const __half2*)&dhu.x;
        const __half2 d23  = *(const __half2*)&dhu.y;
        const __half2 ce01 = *(const __half2*)&ceu.x;
        const __half2 ce23 = *(const __half2*)&ceu.y;

        // e_ij in half2
        const __half2 eij01 = __hadd2(__hadd2(ce01, d01), ex01);
        const __half2 eij23 = __hadd2(__hadd2(ce23, d23), ex23);

        // sigmoid via tanh: sigma = 0.5*tanh(x/2)+0.5
        const __half2 sg01 = __hfma2(tanh_h2(__hmul2(eij01, halfC)), halfC, halfC);
        const __half2 sg23 = __hfma2(tanh_h2(__hmul2(eij23, halfC)), halfC, halfC);

        // gated message
        const __half2 nu01 = __hmul2(sg01, bx01);
        const __half2 nu23 = __hmul2(sg23, bx23);

        __half* np = &g_numh[(size_t)dstI * DIM + n];
        asm volatile("red.global.add.noftz.v2.f16x2 [%0], {%1,%2};"
                     :: "l"(np), "r"(h2u(nu01)), "r"(h2u(nu23)) : "memory");
        __half* dp = &g_denh[(size_t)dstI * DIM + n];
        asm volatile("red.global.add.noftz.v2.f16x2 [%0], {%1,%2};"
                     :: "l"(dp), "r"(h2u(sg01)), "r"(h2u(sg23)) : "memory");

        // e_out = e + relu(BN(e_ij)); BN+relu in half2, residual add in fp32
        const __half2 bn01 = __hmax2(__hfma2(eij01, sH01, hH01), zeroC);
        const __half2 bn23 = __hmax2(__hfma2(eij23, sH23, hH23), zeroC);
        const float2 rb01 = __half22float2(bn01);
        const float2 rb23 = __half22float2(bn23);

        float4 ev;
        asm volatile("ld.global.cs.v4.f32 {%0,%1,%2,%3}, [%4];"
                     : "=f"(ev.x), "=f"(ev.y), "=f"(ev.z), "=f"(ev.w)
                     : "l"(&e[ge * DIM + n]));
        float4 o;
        o.x = ev.x + rb01.x;
        o.y = ev.y + rb01.y;
        o.z = ev.z + rb23.x;
        o.w = ev.w + rb23.y;
        asm volatile("st.global.cs.v4.f32 [%0], {%1,%2,%3,%4};"
                     :: "l"(&e_out[ge * DIM + n]),
                        "f"(o.x), "f"(o.y), "f"(o.z), "f"(o.w)
                     : "memory");
    }
}

// ---------------- kernel 4: node update ----------------
__global__ void update_kernel(const float* __restrict__ x,
                              const float* __restrict__ bxg, const float* __restrict__ bxb,
                              const float* __restrict__ bxm, const float* __restrict__ bxv,
                              float* __restrict__ x_out) {
    const size_t i = (size_t)blockIdx.x * 256 + threadIdx.x;  // 4-column index
    const int c4 = ((int)i & 31) << 2;

    const uint2 nuu = ((const uint2*)g_numh)[i];
    const uint2 deu = ((const uint2*)g_denh)[i];
    const float2 nu01 = __half22float2(*(const __half2*)&nuu.x);
    const float2 nu23 = __half22float2(*(const __half2*)&nuu.y);
    const float2 de01 = __half22float2(*(const __half2*)&deu.x);
    const float2 de23 = __half22float2(*(const __half2*)&deu.y);

    const float4 ax = ((const float4*)g_Ax)[i];
    const float4 xv = ((const float4*)x)[i];

    const float4 gm = *(const float4*)&bxg[c4];
    const float4 bt = *(const float4*)&bxb[c4];
    const float4 mn = *(const float4*)&bxm[c4];
    const float4 vr = *(const float4*)&bxv[c4];

    const float s0 = gm.x * rsqrtf(vr.x + 1e-5f);
    const float s1 = gm.y * rsqrtf(vr.y + 1e-5f);
    const float s2 = gm.z * rsqrtf(vr.z + 1e-5f);
    const float s3 = gm.w * rsqrtf(vr.w + 1e-5f);
    const float h0 = bt.x - mn.x * s0;
    const float h1 = bt.y - mn.y * s1;
    const float h2 = bt.z - mn.z * s2;
    const float h3 = bt.w - mn.w * s3;

    const float v0 = ax.x + nu01.x / (de01.x + 1e-6f);
    const float v1 = ax.y + nu01.y / (de01.y + 1e-6f);
    const float v2 = ax.z + nu23.x / (de23.x + 1e-6f);
    const float v3 = ax.w + nu23.y / (de23.y + 1e-6f);

    float4 o;
    o.x = xv.x + fmaxf(0.f, v0 * s0 + h0);
    o.y = xv.y + fmaxf(0.f, v1 * s1 + h1);
    o.z = xv.z + fmaxf(0.f, v2 * s2 + h2);
    o.w = xv.w + fmaxf(0.f, v3 * s3 + h3);
    asm volatile("st.global.cs.v4.f32 [%0], {%1,%2,%3,%4};"
                 :: "l"(&((float4*)x_out)[i]),
                    "f"(o.x), "f"(o.y), "f"(o.z), "f"(o.w)
                 : "memory");
}

// ---------------- launch ----------------
extern "C" void kernel_launch(void* const* d_in, const int* in_sizes, int n_in,
                              void* d_out, int out_size) {
    const float* x  = (const float*)d_in[0];
    const float* e  = (const float*)d_in[1];
    const float* Aw = (const float*)d_in[2];
    const float* Ab = (const float*)d_in[3];
    const float* Bw = (const float*)d_in[4];
    const float* Bb = (const float*)d_in[5];
    const float* Cw = (const float*)d_in[6];
    const float* Cb = (const float*)d_in[7];
    const float* Dw = (const float*)d_in[8];
    const float* Db = (const float*)d_in[9];
    const float* Ew = (const float*)d_in[10];
    const float* Eb = (const float*)d_in[11];
    const float* bxg = (const float*)d_in[12];
    const float* bxb = (const float*)d_in[13];
    const float* bxm = (const float*)d_in[14];
    const float* bxv = (const float*)d_in[15];
    const float* beg = (const float*)d_in[16];
    const float* beb = (const float*)d_in[17];
    const float* bem = (const float*)d_in[18];
    const float* bev = (const float*)d_in[19];
    const void*  eidx = d_in[20];

    float* x_out = (float*)d_out;
    float* e_out = x_out + (size_t)NN * DIM;

    zero_detect_kernel<<<3125, 256>>>((const unsigned*)eidx);
    // weight order: 0:A 1:B 2:D 3:E 4:C
    prep_kernel<<<dim3(256, 5), 32>>>(Aw, Bw, Dw, Ew, Cw);
    node_gemm_kernel<<<dim3(782, 4), 256, SMEM_TILE>>>(x, Ab, Bb, Db, Eb);
    edge_kernel<<<10000, 256, SMEM_TILE>>>(e, Cb, eidx, beg, beb, bem, bev, e_out);
    update_kernel<<<6250, 256>>>(x, bxg, bxb, bxm, bxv, x_out);
}

// round 14
// speedup vs baseline: 1.3860x; 1.0058x over previous
#include <cuda_runtime.h>
#include <cuda_fp16.h>
#include <cstdint>

#define NN 50000
#define NE 640000
#define DIM 128

// ---------------- scratch (device globals: allocation-free rule) ----------------
__device__ float  g_Ax[NN * DIM];            // A output, fp32
__device__ __half g_Bh[NN * DIM];            // B output, fp16
__device__ __half g_Dh[NN * DIM];            // D output, fp16
__device__ __half g_Eh[NN * DIM];            // E output, fp16
__device__ __half g_numh[NN * DIM];          // fp16 atomic accumulators
__device__ __half g_denh[NN * DIM];
__device__ uint2  g_Wf[5][16 * 16 * 32];     // fragment-packed tf32 weights: A,B,D,E,C
__device__ int    g_i64;

// ---------------- helpers ----------------
__device__ __forceinline__ unsigned f2tf32(float f) {
    unsigned u;
    asm("cvt.rna.tf32.f32 %0, %1;" : "=r"(u) : "f"(f));
    return u;
}

__device__ __forceinline__ void mma_tf32(float c[4], const unsigned a[4],
                                         unsigned b0, unsigned b1) {
    asm volatile(
        "mma.sync.aligned.m16n8k8.row.col.f32.tf32.tf32.f32 "
        "{%0,%1,%2,%3}, {%4,%5,%6,%7}, {%8,%9}, {%0,%1,%2,%3};"
        : "+f"(c[0]), "+f"(c[1]), "+f"(c[2]), "+f"(c[3])
        : "r"(a[0]), "r"(a[1]), "r"(a[2]), "r"(a[3]), "r"(b0), "r"(b1));
}

__device__ __forceinline__ __half2 tanh_h2(__half2 x) {
    __half2 r;
    asm("tanh.approx.f16x2 %0, %1;"
        : "=r"(*reinterpret_cast<unsigned*>(&r))
        : "r"(*reinterpret_cast<const unsigned*>(&x)));
    return r;
}

__device__ __forceinline__ unsigned h2u(__half2 h) {
    return *reinterpret_cast<unsigned*>(&h);
}

// 64x128x128 GEMM core. sA: [64][132] 32-bit operands in smem (tf32 or raw fp32 bits).
__device__ __forceinline__ void gemm_tile(const unsigned* sA, const uint2* __restrict__ Wf,
                                          float acc[2][4][4], int mBase, int nb,
                                          int r, int c, int lane) {
#pragma unroll 4
    for (int ks = 0; ks < 16; ks++) {
        uint2 b[4];
#pragma unroll
        for (int tj = 0; tj < 4; tj++)
            b[tj] = __ldg(&Wf[(ks * 16 + nb + tj) * 32 + lane]);
        unsigned a[2][4];
#pragma unroll
        for (int ti = 0; ti < 2; ti++) {
            const unsigned* ap = &sA[(mBase + ti * 16 + r) * 132 + ks * 8 + c];
            a[ti][0] = ap[0];
            a[ti][1] = ap[8 * 132];
            a[ti][2] = ap[4];
            a[ti][3] = ap[8 * 132 + 4];
        }
#pragma unroll
        for (int ti = 0; ti < 2; ti++)
#pragma unroll
            for (int tj = 0; tj < 4; tj++)
                mma_tf32(acc[ti][tj], a[ti], b[tj].x, b[tj].y);
    }
}

static const int SMEM_TILE = 64 * 132 * 4;  // 33792 B (node + edge kernels)

// ---------------- kernel 0: zero num/den (fp16) + detect edge_index dtype ----------------
__global__ void zero_detect_kernel(const unsigned* __restrict__ w) {
    const size_t i = (size_t)blockIdx.x * 256 + threadIdx.x;  // float4 index (8 halves)
    float4 z = make_float4(0.f, 0.f, 0.f, 0.f);
    ((float4*)g_numh)[i] = z;
    ((float4*)g_denh)[i] = z;
    if (blockIdx.x == 0 && threadIdx.x < 32) {
        unsigned acc = 0;
        for (int k = threadIdx.x; k < 1024; k += 32) acc |= w[2 * k + 1];
#pragma unroll
        for (int o = 16; o; o >>= 1) acc |= __shfl_xor_sync(0xffffffffu, acc, o);
        if (threadIdx.x == 0) g_i64 = (acc == 0) ? 1 : 0;
    }
}

// ---------------- kernel 1: pack weights into fragment layout (tf32) ----------------
__global__ void prep_kernel(const float* __restrict__ W0, const float* __restrict__ W1,
                            const float* __restrict__ W2, const float* __restrict__ W3,
                            const float* __restrict__ W4) {
    const float* Ws[5] = {W0, W1, W2, W3, W4};
    const int lane = threadIdx.x;
    const int g = blockIdx.x;      // ks*16+ng
    const int mat = blockIdx.y;
    const int ks = g >> 4, ng = g & 15;
    const int r = lane >> 2, c = lane & 3;
    const float* W = Ws[mat];
    const int n = ng * 8 + r;
    const int k = ks * 8 + c;
    uint2 v;
    v.x = f2tf32(W[n * DIM + k]);
    v.y = f2tf32(W[n * DIM + k + 4]);
    g_Wf[mat][g * 32 + lane] = v;
}

// ---------------- kernel 2: node GEMMs, one j per block ----------------
// j = blockIdx.y: 0->g_Ax fp32, 1->g_Bh half2, 2->g_Dh half2, 3->g_Eh half2
__global__ void __launch_bounds__(256, 4) node_gemm_kernel(
    const float* __restrict__ x,
    const float* __restrict__ b0, const float* __restrict__ b1,
    const float* __restrict__ b2, const float* __restrict__ b3) {
    extern __shared__ unsigned smem[];
    unsigned* sX = smem;  // 64*132 words (tf32 x tile)

    const int tid = threadIdx.x;
    const int m0 = blockIdx.x * 64;
    const int j = blockIdx.y;

    const float* bias = (j == 0) ? b0 : (j == 1) ? b1 : (j == 2) ? b2 : b3;
    const uint2* Wf = g_Wf[j];

    for (int i = tid; i < 64 * 32; i += 256) {
        int row = i >> 5, c4 = (i & 31) << 2;
        float4 v = make_float4(0.f, 0.f, 0.f, 0.f);
        if (m0 + row < NN) v = *(const float4*)&x[(size_t)(m0 + row) * DIM + c4];
        unsigned* p = &sX[row * 132 + c4];
        p[0] = f2tf32(v.x); p[1] = f2tf32(v.y); p[2] = f2tf32(v.z); p[3] = f2tf32(v.w);
    }
    __syncthreads();

    const int lane = tid & 31, wid = tid >> 5;
    const int r = lane >> 2, c = lane & 3;
    const int mBase = (wid & 1) * 32;
    const int nBase = (wid >> 1) * 32;
    const int nb = (wid >> 1) * 4;

    float acc[2][4][4];
#pragma unroll
    for (int tj = 0; tj < 4; tj++) {
        int n0 = nBase + tj * 8 + c * 2;
        float bv0 = __ldg(&bias[n0]), bv1 = __ldg(&bias[n0 + 1]);
#pragma unroll
        for (int ti = 0; ti < 2; ti++) {
            acc[ti][tj][0] = bv0; acc[ti][tj][1] = bv1;
            acc[ti][tj][2] = bv0; acc[ti][tj][3] = bv1;
        }
    }

    gemm_tile(sX, Wf, acc, mBase, nb, r, c, lane);

    __half* outH = (j == 1) ? g_Bh : (j == 2) ? g_Dh : g_Eh;
#pragma unroll
    for (int ti = 0; ti < 2; ti++) {
#pragma unroll
        for (int half_i = 0; half_i < 2; half_i++) {
            const int m = m0 + mBase + ti * 16 + r + half_i * 8;
            if (m >= NN) continue;
#pragma unroll
            for (int tj = 0; tj < 4; tj++) {
                const int n0 = nBase + tj * 8 + c * 2;
                const float v0 = acc[ti][tj][half_i * 2];
                const float v1 = acc[ti][tj][half_i * 2 + 1];
                if (j == 0) {
                    *(float2*)&g_Ax[(size_t)m * DIM + n0] = make_float2(v0, v1);
                } else {
                    *(__half2*)&outH[(size_t)m * DIM + n0] = __floats2half2_rn(v0, v1);
                }
            }
        }
    }
}

// ---------------- kernel 3: fused edge kernel ----------------
// e staged RAW fp32 (ld.cs, read ONCE). After GEMM, the fp32 tile is compacted
// IN PLACE to fp16: residual -> upper half [16896,33280), Ce fp16 -> lower half.
// Epilogue: all-smem residual + Ce, half2 math, fp16 reds. No global e re-read.
__global__ void __launch_bounds__(256, 4) edge_kernel(
    const float* __restrict__ e,
    const float* __restrict__ Cb,
    const void* __restrict__ eidx,
    const float* __restrict__ beg, const float* __restrict__ beb,
    const float* __restrict__ bem, const float* __restrict__ bev,
    float* __restrict__ e_out) {
    extern __shared__ unsigned smem[];
    float*  sEf = (float*)smem;             // fp32 e tile [64][132], bytes [0,33792)
    __half* sCe = (__half*)smem;            // Ce fp16 [64][132] halves, bytes [0,16896)
    __half* sR  = (__half*)smem + 8448;     // residual fp16 [64][128], bytes [16896,33280)

    const int tid = threadIdx.x;
    const size_t eBase = (size_t)blockIdx.x * 64;
    const uint2* Wf = g_Wf[4];

    // stage e tile: read-once -> evict-first
    for (int i = tid; i < 64 * 32; i += 256) {
        int row = i >> 5, c4 = (i & 31) << 2;
        float4 v;
        asm volatile("ld.global.cs.v4.f32 {%0,%1,%2,%3}, [%4];"
                     : "=f"(v.x), "=f"(v.y), "=f"(v.z), "=f"(v.w)
                     : "l"(&e[(eBase + row) * DIM + c4]));
        float* p = &sEf[row * 132 + c4];
        p[0] = v.x; p[1] = v.y; p[2] = v.z; p[3] = v.w;
    }
    __syncthreads();

    const int lane = tid & 31, wid = tid >> 5;
    const int r = lane >> 2, c = lane & 3;
    const int mBase = (wid & 1) * 32;
    const int nBase = (wid >> 1) * 32;
    const int nb = (wid >> 1) * 4;

    float acc[2][4][4];
#pragma unroll
    for (int tj = 0; tj < 4; tj++) {
        int n0 = nBase + tj * 8 + c * 2;
        float bv0 = __ldg(&Cb[n0]), bv1 = __ldg(&Cb[n0 + 1]);
#pragma unroll
        for (int ti = 0; ti < 2; ti++) {
            acc[ti][tj][0] = bv0; acc[ti][tj][1] = bv1;
            acc[ti][tj][2] = bv0; acc[ti][tj][3] = bv1;
        }
    }

    gemm_tile((const unsigned*)smem, Wf, acc, mBase, nb, r, c, lane);
    __syncthreads();  // GEMM reads of sEf complete

    // ---- in-place fp32 -> fp16 compaction, rows high -> low (overlap-safe) ----
    // thread covers row = rbase + tid/16, cols 8t..8t+7 (t = tid%16)
    {
        const int prow = tid >> 4;
        const int t = tid & 15;
#pragma unroll
        for (int ph = 3; ph >= 0; ph--) {
            const int row = ph * 16 + prow;
            const float4 v0 = *(const float4*)&sEf[row * 132 + 8 * t];
            const float4 v1 = *(const float4*)&sEf[row * 132 + 8 * t + 4];
            __syncthreads();  // all reads of this phase's (and overlapping) fp32 done
            uint4 o;
            o.x = h2u(__floats2half2_rn(v0.x, v0.y));
            o.y = h2u(__floats2half2_rn(v0.z, v0.w));
            o.z = h2u(__floats2half2_rn(v1.x, v1.y));
            o.w = h2u(__floats2half2_rn(v1.z, v1.w));
            *(uint4*)&sR[row * 128 + 8 * t] = o;
            __syncthreads();
        }
    }

    // ---- Ce fp16 store into lower half (fp32 rows 0-31 already consumed) ----
#pragma unroll
    for (int ti = 0; ti < 2; ti++) {
        int m = mBase + ti * 16 + r;
#pragma unroll
        for (int tj = 0; tj < 4; tj++) {
            int n0 = nBase + tj * 8 + c * 2;
            *(__half2*)&sCe[m * 132 + n0] =
                __floats2half2_rn(acc[ti][tj][0], acc[ti][tj][1]);
            *(__half2*)&sCe[(m + 8) * 132 + n0] =
                __floats2half2_rn(acc[ti][tj][2], acc[ti][tj][3]);
        }
    }
    __syncthreads();

    // ---- epilogue: warp w handles edges w*8..w*8+7, lane owns cols 4*lane..+3
    const int n = lane * 4;
    const float4 gm = *(const float4*)&beg[n];
    const float4 bt = *(const float4*)&beb[n];
    const float4 mn = *(const float4*)&bem[n];
    const float4 vr = *(const float4*)&bev[n];
    const float s0c = gm.x * rsqrtf(vr.x + 1e-5f);
    const float s1c = gm.y * rsqrtf(vr.y + 1e-5f);
    const float s2c = gm.z * rsqrtf(vr.z + 1e-5f);
    const float s3c = gm.w * rsqrtf(vr.w + 1e-5f);
    const __half2 sH01 = __floats2half2_rn(s0c, s1c);
    const __half2 sH23 = __floats2half2_rn(s2c, s3c);
    const __half2 hH01 = __floats2half2_rn(bt.x - mn.x * s0c, bt.y - mn.y * s1c);
    const __half2 hH23 = __floats2half2_rn(bt.z - mn.z * s2c, bt.w - mn.w * s3c);
    const __half2 halfC = __floats2half2_rn(0.5f, 0.5f);
    const __half2 zeroC = __floats2half2_rn(0.f, 0.f);

    const int flag = g_i64;
    const long long* i64p = (const long long*)eidx;
    const int* i32p = (const int*)eidx;

    int srcs[8], dsts[8];
    if (flag) {
#pragma unroll
        for (int mi = 0; mi < 8; mi++) {
            const size_t ge = eBase + wid * 8 + mi;
            srcs[mi] = (int)__ldg(&i64p[ge]);
            dsts[mi] = (int)__ldg(&i64p[NE + ge]);
        }
    } else {
#pragma unroll
        for (int mi = 0; mi < 8; mi++) {
            const size_t ge = eBase + wid * 8 + mi;
            srcs[mi] = __ldg(&i32p[ge]);
            dsts[mi] = __ldg(&i32p[NE + ge]);
        }
    }

#pragma unroll
    for (int mi = 0; mi < 8; mi++) {
        const int m = wid * 8 + mi;
        const size_t ge = eBase + m;
        const int srcI = srcs[mi], dstI = dsts[mi];

        const uint2 exu = __ldg((const uint2*)&g_Eh[(size_t)srcI * DIM + n]);
        const uint2 bxu = __ldg((const uint2*)&g_Bh[(size_t)srcI * DIM + n]);
        const uint2 dhu = __ldg((const uint2*)&g_Dh[(size_t)dstI * DIM + n]);
        const uint2 ceu = *(const uint2*)&sCe[m * 132 + n];
        const uint2 ru  = *(const uint2*)&sR[m * 128 + n];

        const __half2 ex01 = *(const __half2*)&exu.x;
        const __half2 ex23 = *(const __half2*)&exu.y;
        const __half2 bx01 = *(const __half2*)&bxu.x;
        const __half2 bx23 = *(const __half2*)&bxu.y;
        const __half2 d01  = *(const __half2*)&dhu.x;
        const __half2 d23  = *(const __half2*)&dhu.y;
        const __half2 ce01 = *(const __half2*)&ceu.x;
        const __half2 ce23 = *(const __half2*)&ceu.y;

        // e_ij in half2
        const __half2 eij01 = __hadd2(__hadd2(ce01, d01), ex01);
        const __half2 eij23 = __hadd2(__hadd2(ce23, d23), ex23);

        // sigmoid via tanh: sigma = 0.5*tanh(x/2)+0.5
        const __half2 sg01 = __hfma2(tanh_h2(__hmul2(eij01, halfC)), halfC, halfC);
        const __half2 sg23 = __hfma2(tanh_h2(__hmul2(eij23, halfC)), halfC, halfC);

        // gated message
        const __half2 nu01 = __hmul2(sg01, bx01);
        const __half2 nu23 = __hmul2(sg23, bx23);

        __half* np = &g_numh[(size_t)dstI * DIM + n];
        asm volatile("red.global.add.noftz.v2.f16x2 [%0], {%1,%2};"
                     :: "l"(np), "r"(h2u(nu01)), "r"(h2u(nu23)) : "memory");
        __half* dp = &g_denh[(size_t)dstI * DIM + n];
        asm volatile("red.global.add.noftz.v2.f16x2 [%0], {%1,%2};"
                     :: "l"(dp), "r"(h2u(sg01)), "r"(h2u(sg23)) : "memory");

        // e_out = e + relu(BN(e_ij)); residual from smem fp16, add in fp32
        const __half2 bn01 = __hmax2(__hfma2(eij01, sH01, hH01), zeroC);
        const __half2 bn23 = __hmax2(__hfma2(eij23, sH23, hH23), zeroC);
        const float2 rb01 = __half22float2(bn01);
        const float2 rb23 = __half22float2(bn23);
        const float2 r01 = __half22float2(*(const __half2*)&ru.x);
        const float2 r23 = __half22float2(*(const __half2*)&ru.y);

        float4 o;
        o.x = r01.x + rb01.x;
        o.y = r01.y + rb01.y;
        o.z = r23.x + rb23.x;
        o.w = r23.y + rb23.y;
        asm volatile("st.global.cs.v4.f32 [%0], {%1,%2,%3,%4};"
                     :: "l"(&e_out[ge * DIM + n]),
                        "f"(o.x), "f"(o.y), "f"(o.z), "f"(o.w)
                     : "memory");
    }
}

// ---------------- kernel 4: node update ----------------
__global__ void update_kernel(const float* __restrict__ x,
                              const float* __restrict__ bxg, const float* __restrict__ bxb,
                              const float* __restrict__ bxm, const float* __restrict__ bxv,
                              float* __restrict__ x_out) {
    const size_t i = (size_t)blockIdx.x * 256 + threadIdx.x;  // 4-column index
    const int c4 = ((int)i & 31) << 2;

    const uint2 nuu = ((const uint2*)g_numh)[i];
    const uint2 deu = ((const uint2*)g_denh)[i];
    const float2 nu01 = __half22float2(*(const __half2*)&nuu.x);
    const float2 nu23 = __half22float2(*(const __half2*)&nuu.y);
    const float2 de01 = __half22float2(*(const __half2*)&deu.x);
    const float2 de23 = __half22float2(*(const __half2*)&deu.y);

    const float4 ax = ((const float4*)g_Ax)[i];
    const float4 xv = ((const float4*)x)[i];

    const float4 gm = *(const float4*)&bxg[c4];
    const float4 bt = *(const float4*)&bxb[c4];
    const float4 mn = *(const float4*)&bxm[c4];
    const float4 vr = *(const float4*)&bxv[c4];

    const float s0 = gm.x * rsqrtf(vr.x + 1e-5f);
    const float s1 = gm.y * rsqrtf(vr.y + 1e-5f);
    const float s2 = gm.z * rsqrtf(vr.z + 1e-5f);
    const float s3 = gm.w * rsqrtf(vr.w + 1e-5f);
    const float h0 = bt.x - mn.x * s0;
    const float h1 = bt.y - mn.y * s1;
    const float h2 = bt.z - mn.z * s2;
    const float h3 = bt.w - mn.w * s3;

    const float v0 = ax.x + nu01.x / (de01.x + 1e-6f);
    const float v1 = ax.y + nu01.y / (de01.y + 1e-6f);
    const float v2 = ax.z + nu23.x / (de23.x + 1e-6f);
    const float v3 = ax.w + nu23.y / (de23.y + 1e-6f);

    float4 o;
    o.x = xv.x + fmaxf(0.f, v0 * s0 + h0);
    o.y = xv.y + fmaxf(0.f, v1 * s1 + h1);
    o.z = xv.z + fmaxf(0.f, v2 * s2 + h2);
    o.w = xv.w + fmaxf(0.f, v3 * s3 + h3);
    asm volatile("st.global.cs.v4.f32 [%0], {%1,%2,%3,%4};"
                 :: "l"(&((float4*)x_out)[i]),
                    "f"(o.x), "f"(o.y), "f"(o.z), "f"(o.w)
                 : "memory");
}

// ---------------- launch ----------------
extern "C" void kernel_launch(void* const* d_in, const int* in_sizes, int n_in,
                              void* d_out, int out_size) {
    const float* x  = (const float*)d_in[0];
    const float* e  = (const float*)d_in[1];
    const float* Aw = (const float*)d_in[2];
    const float* Ab = (const float*)d_in[3];
    const float* Bw = (const float*)d_in[4];
    const float* Bb = (const float*)d_in[5];
    const float* Cw = (const float*)d_in[6];
    const float* Cb = (const float*)d_in[7];
    const float* Dw = (const float*)d_in[8];
    const float* Db = (const float*)d_in[9];
    const float* Ew = (const float*)d_in[10];
    const float* Eb = (const float*)d_in[11];
    const float* bxg = (const float*)d_in[12];
    const float* bxb = (const float*)d_in[13];
    const float* bxm = (const float*)d_in[14];
    const float* bxv = (const float*)d_in[15];
    const float* beg = (const float*)d_in[16];
    const float* beb = (const float*)d_in[17];
    const float* bem = (const float*)d_in[18];
    const float* bev = (const float*)d_in[19];
    const void*  eidx = d_in[20];

    float* x_out = (float*)d_out;
    float* e_out = x_out + (size_t)NN * DIM;

    zero_detect_kernel<<<3125, 256>>>((const unsigned*)eidx);
    // weight order: 0:A 1:B 2:D 3:E 4:C
    prep_kernel<<<dim3(256, 5), 32>>>(Aw, Bw, Dw, Ew, Cw);
    node_gemm_kernel<<<dim3(782, 4), 256, SMEM_TILE>>>(x, Ab, Bb, Db, Eb);
    edge_kernel<<<10000, 256, SMEM_TILE>>>(e, Cb, eidx, beg, beb, bem, bev, e_out);
    update_kernel<<<6250, 256>>>(x, bxg, bxb, bxm, bxv, x_out);
}

// round 15
// speedup vs baseline: 1.7229x; 1.2431x over previous
#include <cuda_runtime.h>
#include <cuda_fp16.h>
#include <cstdint>

#define NN 50000
#define NE 640000
#define DIM 128

// ---------------- scratch (device globals: allocation-free rule) ----------------
__device__ float  g_Ax[NN * DIM];            // A output, fp32
__device__ __half g_Bh[NN * DIM];            // B output, fp16
__device__ __half g_Dh[NN * DIM];            // D output, fp16
__device__ __half g_Eh[NN * DIM];            // E output, fp16
__device__ __half g_numh[NN * DIM];          // fp16 atomic accumulators
__device__ __half g_denh[NN * DIM];
__device__ uint2  g_Wfh[5][8 * 16 * 32];     // fragment-packed fp16 weights (m16n8k16): A,B,D,E,C
__device__ int    g_i64;

// ---------------- helpers ----------------
__device__ __forceinline__ unsigned h2u(__half2 h) {
    return *reinterpret_cast<unsigned*>(&h);
}

__device__ __forceinline__ void mma_f16(float c[4], const unsigned a[4],
                                        unsigned b0, unsigned b1) {
    asm volatile(
        "mma.sync.aligned.m16n8k16.row.col.f32.f16.f16.f32 "
        "{%0,%1,%2,%3}, {%4,%5,%6,%7}, {%8,%9}, {%0,%1,%2,%3};"
        : "+f"(c[0]), "+f"(c[1]), "+f"(c[2]), "+f"(c[3])
        : "r"(a[0]), "r"(a[1]), "r"(a[2]), "r"(a[3]), "r"(b0), "r"(b1));
}

__device__ __forceinline__ __half2 tanh_h2(__half2 x) {
    __half2 r;
    asm("tanh.approx.f16x2 %0, %1;"
        : "=r"(*reinterpret_cast<unsigned*>(&r))
        : "r"(*reinterpret_cast<const unsigned*>(&x)));
    return r;
}

// 64x128x128 fp16 GEMM core. sA: [64][136] fp16 in smem (row stride 136 halves = 68 words,
// conflict-free). Weights streamed from fragment-packed fp16 globals (L1-hot, 32KB).
// m16n8k16: 8 k-steps. D-fragment layout identical to m16n8k8 (epilogues unchanged).
__device__ __forceinline__ void gemm_tile_h(const __half* sA, const uint2* __restrict__ Wfh,
                                            float acc[2][4][4], int mBase, int nb,
                                            int r, int c, int lane) {
#pragma unroll
    for (int ks = 0; ks < 8; ks++) {
        uint2 b[4];
#pragma unroll
        for (int tj = 0; tj < 4; tj++)
            b[tj] = __ldg(&Wfh[(ks * 16 + nb + tj) * 32 + lane]);
        unsigned a[2][4];
#pragma unroll
        for (int ti = 0; ti < 2; ti++) {
            const __half* ap = &sA[(mBase + ti * 16 + r) * 136 + ks * 16 + c * 2];
            a[ti][0] = *(const unsigned*)ap;               // {A[r][k0], A[r][k0+1]}
            a[ti][1] = *(const unsigned*)(ap + 8 * 136);   // {A[r+8][k0], ...}
            a[ti][2] = *(const unsigned*)(ap + 8);         // {A[r][k0+8], ...}
            a[ti][3] = *(const unsigned*)(ap + 8 * 136 + 8);
        }
#pragma unroll
        for (int ti = 0; ti < 2; ti++)
#pragma unroll
            for (int tj = 0; tj < 4; tj++)
                mma_f16(acc[ti][tj], a[ti], b[tj].x, b[tj].y);
    }
}

static const int SMEM_NODE = 64 * 136 * 2;      // 17408 B (x tile)
static const int SMEM_EDGE = 64 * 136 * 2 * 2;  // 34816 B (e tile + Ce tile)

// ---------------- kernel 0: zero num/den (fp16) + detect edge_index dtype ----------------
__global__ void zero_detect_kernel(const unsigned* __restrict__ w) {
    const size_t i = (size_t)blockIdx.x * 256 + threadIdx.x;  // float4 index (8 halves)
    float4 z = make_float4(0.f, 0.f, 0.f, 0.f);
    ((float4*)g_numh)[i] = z;
    ((float4*)g_denh)[i] = z;
    if (blockIdx.x == 0 && threadIdx.x < 32) {
        unsigned acc = 0;
        for (int k = threadIdx.x; k < 1024; k += 32) acc |= w[2 * k + 1];
#pragma unroll
        for (int o = 16; o; o >>= 1) acc |= __shfl_xor_sync(0xffffffffu, acc, o);
        if (threadIdx.x == 0) g_i64 = (acc == 0) ? 1 : 0;
    }
}

// ---------------- kernel 1: pack weights into fp16 fragment layout (m16n8k16 B) ----------------
// n = ng*8 + lane/4, k0 = ks*16 + (lane%4)*2; uint2 = { {W[n][k0],W[n][k0+1]}, {W[n][k0+8],W[n][k0+9]} }
__global__ void prep_kernel(const float* __restrict__ W0, const float* __restrict__ W1,
                            const float* __restrict__ W2, const float* __restrict__ W3,
                            const float* __restrict__ W4) {
    const float* Ws[5] = {W0, W1, W2, W3, W4};
    const int lane = threadIdx.x;
    const int g = blockIdx.x;      // ks*16+ng, ks in [0,8)
    const int mat = blockIdx.y;
    const float* W = Ws[mat];
    const int n = (g & 15) * 8 + (lane >> 2);
    const int k0 = (g >> 4) * 16 + (lane & 3) * 2;
    uint2 v;
    v.x = h2u(__floats2half2_rn(W[n * DIM + k0],     W[n * DIM + k0 + 1]));
    v.y = h2u(__floats2half2_rn(W[n * DIM + k0 + 8], W[n * DIM + k0 + 9]));
    g_Wfh[mat][g * 32 + lane] = v;
}

// ---------------- kernel 2: node GEMMs, one j per block ----------------
// j = blockIdx.y: 0->g_Ax fp32, 1->g_Bh half2, 2->g_Dh half2, 3->g_Eh half2
__global__ void __launch_bounds__(256, 4) node_gemm_kernel(
    const float* __restrict__ x,
    const float* __restrict__ b0, const float* __restrict__ b1,
    const float* __restrict__ b2, const float* __restrict__ b3) {
    extern __shared__ __half smemh[];
    __half* sX = smemh;  // [64][136] fp16 x tile

    const int tid = threadIdx.x;
    const int m0 = blockIdx.x * 64;
    const int j = blockIdx.y;

    const float* bias = (j == 0) ? b0 : (j == 1) ? b1 : (j == 2) ? b2 : b3;
    const uint2* Wfh = g_Wfh[j];

    for (int i = tid; i < 64 * 32; i += 256) {
        int row = i >> 5, c4 = (i & 31) << 2;
        float4 v = make_float4(0.f, 0.f, 0.f, 0.f);
        if (m0 + row < NN) v = *(const float4*)&x[(size_t)(m0 + row) * DIM + c4];
        uint2 u;
        u.x = h2u(__floats2half2_rn(v.x, v.y));
        u.y = h2u(__floats2half2_rn(v.z, v.w));
        *(uint2*)&sX[row * 136 + c4] = u;
    }
    __syncthreads();

    const int lane = tid & 31, wid = tid >> 5;
    const int r = lane >> 2, c = lane & 3;
    const int mBase = (wid & 1) * 32;
    const int nBase = (wid >> 1) * 32;
    const int nb = (wid >> 1) * 4;

    float acc[2][4][4];
#pragma unroll
    for (int tj = 0; tj < 4; tj++) {
        int n0 = nBase + tj * 8 + c * 2;
        float bv0 = __ldg(&bias[n0]), bv1 = __ldg(&bias[n0 + 1]);
#pragma unroll
        for (int ti = 0; ti < 2; ti++) {
            acc[ti][tj][0] = bv0; acc[ti][tj][1] = bv1;
            acc[ti][tj][2] = bv0; acc[ti][tj][3] = bv1;
        }
    }

    gemm_tile_h(sX, Wfh, acc, mBase, nb, r, c, lane);

    __half* outH = (j == 1) ? g_Bh : (j == 2) ? g_Dh : g_Eh;
#pragma unroll
    for (int ti = 0; ti < 2; ti++) {
#pragma unroll
        for (int half_i = 0; half_i < 2; half_i++) {
            const int m = m0 + mBase + ti * 16 + r + half_i * 8;
            if (m >= NN) continue;
#pragma unroll
            for (int tj = 0; tj < 4; tj++) {
                const int n0 = nBase + tj * 8 + c * 2;
                const float v0 = acc[ti][tj][half_i * 2];
                const float v1 = acc[ti][tj][half_i * 2 + 1];
                if (j == 0) {
                    *(float2*)&g_Ax[(size_t)m * DIM + n0] = make_float2(v0, v1);
                } else {
                    *(__half2*)&outH[(size_t)m * DIM + n0] = __floats2half2_rn(v0, v1);
                }
            }
        }
    }
}

// ---------------- kernel 3: fused edge kernel, fp16 GEMM ----------------
// e staged ONCE as fp16 (serves both GEMM A-operand and residual). Ce fp16 in a
// separate smem region. 2 syncthreads total. Half2 epilogue, fp16 reds.
__global__ void __launch_bounds__(256, 4) edge_kernel(
    const float* __restrict__ e,
    const float* __restrict__ Cb,
    const void* __restrict__ eidx,
    const float* __restrict__ beg, const float* __restrict__ beb,
    const float* __restrict__ bem, const float* __restrict__ bev,
    float* __restrict__ e_out) {
    extern __shared__ __half smemh[];
    __half* sEh = smemh;               // [64][136] fp16 e tile (GEMM A + residual)
    __half* sCe = smemh + 64 * 136;    // [64][136] fp16 Ce tile

    const int tid = threadIdx.x;
    const size_t eBase = (size_t)blockIdx.x * 64;
    const uint2* Wfh = g_Wfh[4];

    // stage e tile as fp16: read-once global -> evict-first
    for (int i = tid; i < 64 * 32; i += 256) {
        int row = i >> 5, c4 = (i & 31) << 2;
        float4 v;
        asm volatile("ld.global.cs.v4.f32 {%0,%1,%2,%3}, [%4];"
                     : "=f"(v.x), "=f"(v.y), "=f"(v.z), "=f"(v.w)
                     : "l"(&e[(eBase + row) * DIM + c4]));
        uint2 u;
        u.x = h2u(__floats2half2_rn(v.x, v.y));
        u.y = h2u(__floats2half2_rn(v.z, v.w));
        *(uint2*)&sEh[row * 136 + c4] = u;
    }
    __syncthreads();

    const int lane = tid & 31, wid = tid >> 5;
    const int r = lane >> 2, c = lane & 3;
    const int mBase = (wid & 1) * 32;
    const int nBase = (wid >> 1) * 32;
    const int nb = (wid >> 1) * 4;

    float acc[2][4][4];
#pragma unroll
    for (int tj = 0; tj < 4; tj++) {
        int n0 = nBase + tj * 8 + c * 2;
        float bv0 = __ldg(&Cb[n0]), bv1 = __ldg(&Cb[n0 + 1]);
#pragma unroll
        for (int ti = 0; ti < 2; ti++) {
            acc[ti][tj][0] = bv0; acc[ti][tj][1] = bv1;
            acc[ti][tj][2] = bv0; acc[ti][tj][3] = bv1;
        }
    }

    gemm_tile_h(sEh, Wfh, acc, mBase, nb, r, c, lane);

    // Ce fp16 into its own region (no WAR on sEh)
#pragma unroll
    for (int ti = 0; ti < 2; ti++) {
        int m = mBase + ti * 16 + r;
#pragma unroll
        for (int tj = 0; tj < 4; tj++) {
            int n0 = nBase + tj * 8 + c * 2;
            *(__half2*)&sCe[m * 136 + n0] =
                __floats2half2_rn(acc[ti][tj][0], acc[ti][tj][1]);
            *(__half2*)&sCe[(m + 8) * 136 + n0] =
                __floats2half2_rn(acc[ti][tj][2], acc[ti][tj][3]);
        }
    }
    __syncthreads();

    // ---- epilogue: warp w handles edges w*8..w*8+7, lane owns cols 4*lane..+3
    const int n = lane * 4;
    const float4 gm = *(const float4*)&beg[n];
    const float4 bt = *(const float4*)&beb[n];
    const float4 mn = *(const float4*)&bem[n];
    const float4 vr = *(const float4*)&bev[n];
    const float s0c = gm.x * rsqrtf(vr.x + 1e-5f);
    const float s1c = gm.y * rsqrtf(vr.y + 1e-5f);
    const float s2c = gm.z * rsqrtf(vr.z + 1e-5f);
    const float s3c = gm.w * rsqrtf(vr.w + 1e-5f);
    const __half2 sH01 = __floats2half2_rn(s0c, s1c);
    const __half2 sH23 = __floats2half2_rn(s2c, s3c);
    const __half2 hH01 = __floats2half2_rn(bt.x - mn.x * s0c, bt.y - mn.y * s1c);
    const __half2 hH23 = __floats2half2_rn(bt.z - mn.z * s2c, bt.w - mn.w * s3c);
    const __half2 halfC = __floats2half2_rn(0.5f, 0.5f);
    const __half2 zeroC = __floats2half2_rn(0.f, 0.f);

    const int flag = g_i64;
    const long long* i64p = (const long long*)eidx;
    const int* i32p = (const int*)eidx;

    int srcs[8], dsts[8];
    if (flag) {
#pragma unroll
        for (int mi = 0; mi < 8; mi++) {
            const size_t ge = eBase + wid * 8 + mi;
            srcs[mi] = (int)__ldg(&i64p[ge]);
            dsts[mi] = (int)__ldg(&i64p[NE + ge]);
        }
    } else {
#pragma unroll
        for (int mi = 0; mi < 8; mi++) {
            const size_t ge = eBase + wid * 8 + mi;
            srcs[mi] = __ldg(&i32p[ge]);
            dsts[mi] = __ldg(&i32p[NE + ge]);
        }
    }

#pragma unroll
    for (int mi = 0; mi < 8; mi++) {
        const int m = wid * 8 + mi;
        const size_t ge = eBase + m;
        const int srcI = srcs[mi], dstI = dsts[mi];

        const uint2 exu = __ldg((const uint2*)&g_Eh[(size_t)srcI * DIM + n]);
        const uint2 bxu = __ldg((const uint2*)&g_Bh[(size_t)srcI * DIM + n]);
        const uint2 dhu = __ldg((const uint2*)&g_Dh[(size_t)dstI * DIM + n]);
        const uint2 ceu = *(const uint2*)&sCe[m * 136 + n];
        const uint2 ru  = *(const uint2*)&sEh[m * 136 + n];

        const __half2 ex01 = *(const __half2*)&exu.x;
        const __half2 ex23 = *(const __half2*)&exu.y;
        const __half2 bx01 = *(const __half2*)&bxu.x;
        const __half2 bx23 = *(const __half2*)&bxu.y;
        const __half2 d01  = *(const __half2*)&dhu.x;
        const __half2 d23  = *(const __half2*)&dhu.y;
        const __half2 ce01 = *(const __half2*)&ceu.x;
        const __half2 ce23 = *(const __half2*)&ceu.y;

        // e_ij in half2
        const __half2 eij01 = __hadd2(__hadd2(ce01, d01), ex01);
        const __half2 eij23 = __hadd2(__hadd2(ce23, d23), ex23);

        // sigmoid via tanh: sigma = 0.5*tanh(x/2)+0.5
        const __half2 sg01 = __hfma2(tanh_h2(__hmul2(eij01, halfC)), halfC, halfC);
        const __half2 sg23 = __hfma2(tanh_h2(__hmul2(eij23, halfC)), halfC, halfC);

        // gated message
        const __half2 nu01 = __hmul2(sg01, bx01);
        const __half2 nu23 = __hmul2(sg23, bx23);

        __half* np = &g_numh[(size_t)dstI * DIM + n];
        asm volatile("red.global.add.noftz.v2.f16x2 [%0], {%1,%2};"
                     :: "l"(np), "r"(h2u(nu01)), "r"(h2u(nu23)) : "memory");
        __half* dp = &g_denh[(size_t)dstI * DIM + n];
        asm volatile("red.global.add.noftz.v2.f16x2 [%0], {%1,%2};"
                     :: "l"(dp), "r"(h2u(sg01)), "r"(h2u(sg23)) : "memory");

        // e_out = e + relu(BN(e_ij)); residual from smem fp16, add in fp32
        const __half2 bn01 = __hmax2(__hfma2(eij01, sH01, hH01), zeroC);
        const __half2 bn23 = __hmax2(__hfma2(eij23, sH23, hH23), zeroC);
        const float2 rb01 = __half22float2(bn01);
        const float2 rb23 = __half22float2(bn23);
        const float2 r01 = __half22float2(*(const __half2*)&ru.x);
        const float2 r23 = __half22float2(*(const __half2*)&ru.y);

        float4 o;
        o.x = r01.x + rb01.x;
        o.y = r01.y + rb01.y;
        o.z = r23.x + rb23.x;
        o.w = r23.y + rb23.y;
        asm volatile("st.global.cs.v4.f32 [%0], {%1,%2,%3,%4};"
                     :: "l"(&e_out[ge * DIM + n]),
                        "f"(o.x), "f"(o.y), "f"(o.z), "f"(o.w)
                     : "memory");
    }
}

// ---------------- kernel 4: node update ----------------
__global__ void update_kernel(const float* __restrict__ x,
                              const float* __restrict__ bxg, const float* __restrict__ bxb,
                              const float* __restrict__ bxm, const float* __restrict__ bxv,
                              float* __restrict__ x_out) {
    const size_t i = (size_t)blockIdx.x * 256 + threadIdx.x;  // 4-column index
    const int c4 = ((int)i & 31) << 2;

    const uint2 nuu = ((const uint2*)g_numh)[i];
    const uint2 deu = ((const uint2*)g_denh)[i];
    const float2 nu01 = __half22float2(*(const __half2*)&nuu.x);
    const float2 nu23 = __half22float2(*(const __half2*)&nuu.y);
    const float2 de01 = __half22float2(*(const __half2*)&deu.x);
    const float2 de23 = __half22float2(*(const __half2*)&deu.y);

    const float4 ax = ((const float4*)g_Ax)[i];
    const float4 xv = ((const float4*)x)[i];

    const float4 gm = *(const float4*)&bxg[c4];
    const float4 bt = *(const float4*)&bxb[c4];
    const float4 mn = *(const float4*)&bxm[c4];
    const float4 vr = *(const float4*)&bxv[c4];

    const float s0 = gm.x * rsqrtf(vr.x + 1e-5f);
    const float s1 = gm.y * rsqrtf(vr.y + 1e-5f);
    const float s2 = gm.z * rsqrtf(vr.z + 1e-5f);
    const float s3 = gm.w * rsqrtf(vr.w + 1e-5f);
    const float h0 = bt.x - mn.x * s0;
    const float h1 = bt.y - mn.y * s1;
    const float h2 = bt.z - mn.z * s2;
    const float h3 = bt.w - mn.w * s3;

    const float v0 = ax.x + nu01.x / (de01.x + 1e-6f);
    const float v1 = ax.y + nu01.y / (de01.y + 1e-6f);
    const float v2 = ax.z + nu23.x / (de23.x + 1e-6f);
    const float v3 = ax.w + nu23.y / (de23.y + 1e-6f);

    float4 o;
    o.x = xv.x + fmaxf(0.f, v0 * s0 + h0);
    o.y = xv.y + fmaxf(0.f, v1 * s1 + h1);
    o.z = xv.z + fmaxf(0.f, v2 * s2 + h2);
    o.w = xv.w + fmaxf(0.f, v3 * s3 + h3);
    asm volatile("st.global.cs.v4.f32 [%0], {%1,%2,%3,%4};"
                 :: "l"(&((float4*)x_out)[i]),
                    "f"(o.x), "f"(o.y), "f"(o.z), "f"(o.w)
                 : "memory");
}

// ---------------- launch ----------------
extern "C" void kernel_launch(void* const* d_in, const int* in_sizes, int n_in,
                              void* d_out, int out_size) {
    const float* x  = (const float*)d_in[0];
    const float* e  = (const float*)d_in[1];
    const float* Aw = (const float*)d_in[2];
    const float* Ab = (const float*)d_in[3];
    const float* Bw = (const float*)d_in[4];
    const float* Bb = (const float*)d_in[5];
    const float* Cw = (const float*)d_in[6];
    const float* Cb = (const float*)d_in[7];
    const float* Dw = (const float*)d_in[8];
    const float* Db = (const float*)d_in[9];
    const float* Ew = (const float*)d_in[10];
    const float* Eb = (const float*)d_in[11];
    const float* bxg = (const float*)d_in[12];
    const float* bxb = (const float*)d_in[13];
    const float* bxm = (const float*)d_in[14];
    const float* bxv = (const float*)d_in[15];
    const float* beg = (const float*)d_in[16];
    const float* beb = (const float*)d_in[17];
    const float* bem = (const float*)d_in[18];
    const float* bev = (const float*)d_in[19];
    const void*  eidx = d_in[20];

    float* x_out = (float*)d_out;
    float* e_out = x_out + (size_t)NN * DIM;

    zero_detect_kernel<<<3125, 256>>>((const unsigned*)eidx);
    // weight order: 0:A 1:B 2:D 3:E 4:C  (fp16 fragments, 8 k-steps)
    prep_kernel<<<dim3(128, 5), 32>>>(Aw, Bw, Dw, Ew, Cw);
    node_gemm_kernel<<<dim3(782, 4), 256, SMEM_NODE>>>(x, Ab, Bb, Db, Eb);
    edge_kernel<<<10000, 256, SMEM_EDGE>>>(e, Cb, eidx, beg, beb, bem, bev, e_out);
    update_kernel<<<6250, 256>>>(x, bxg, bxb, bxm, bxv, x_out);
}

// round 17
// speedup vs baseline: 1.7493x; 1.0153x over previous
#include <cuda_runtime.h>
#include <cuda_fp16.h>
#include <cstdint>

#define NN 50000
#define NE 640000
#define DIM 128

// ---------------- scratch (device globals: allocation-free rule) ----------------
__device__ float  g_Ax[NN * DIM];            // A output, fp32
__device__ __half g_Bh[NN * DIM];            // B output, fp16
__device__ __half g_Dh[NN * DIM];            // D output, fp16
__device__ __half g_Eh[NN * DIM];            // E output, fp16
__device__ __half g_numh[NN * DIM];          // fp16 atomic accumulators
__device__ __half g_denh[NN * DIM];
__device__ uint2  g_Wfh[5][8 * 16 * 32];     // fragment-packed fp16 weights (m16n8k16): A,B,D,E,C
__device__ int    g_i64;

// ---------------- helpers ----------------
__device__ __forceinline__ unsigned h2u(__half2 h) {
    return *reinterpret_cast<unsigned*>(&h);
}

__device__ __forceinline__ void mma_f16(float c[4], const unsigned a[4],
                                        unsigned b0, unsigned b1) {
    asm volatile(
        "mma.sync.aligned.m16n8k16.row.col.f32.f16.f16.f32 "
        "{%0,%1,%2,%3}, {%4,%5,%6,%7}, {%8,%9}, {%0,%1,%2,%3};"
        : "+f"(c[0]), "+f"(c[1]), "+f"(c[2]), "+f"(c[3])
        : "r"(a[0]), "r"(a[1]), "r"(a[2]), "r"(a[3]), "r"(b0), "r"(b1));
}

__device__ __forceinline__ __half2 tanh_h2(__half2 x) {
    __half2 r;
    asm("tanh.approx.f16x2 %0, %1;"
        : "=r"(*reinterpret_cast<unsigned*>(&r))
        : "r"(*reinterpret_cast<const unsigned*>(&x)));
    return r;
}

// L2 evict-last cache policy (created once per thread, reused for all gathers)
__device__ __forceinline__ uint64_t make_evict_last_policy() {
    uint64_t pol;
    asm("createpolicy.fractional.L2::evict_last.b64 %0, 1.0;" : "=l"(pol));
    return pol;
}

// gather load with L2 evict-last priority via cache_hint (any width allowed)
__device__ __forceinline__ uint2 ldg_el_u2(const __half* p, uint64_t pol) {
    uint2 v;
    asm volatile("ld.global.nc.L2::cache_hint.v2.u32 {%0,%1}, [%2], %3;"
                 : "=r"(v.x), "=r"(v.y) : "l"(p), "l"(pol));
    return v;
}

// 64x128x128 fp16 GEMM core. sA: [64][136] fp16 in smem (row stride 136 halves = 68 words,
// conflict-free). Weights streamed from fragment-packed fp16 globals (L1-hot, 32KB).
__device__ __forceinline__ void gemm_tile_h(const __half* sA, const uint2* __restrict__ Wfh,
                                            float acc[2][4][4], int mBase, int nb,
                                            int r, int c, int lane) {
#pragma unroll
    for (int ks = 0; ks < 8; ks++) {
        uint2 b[4];
#pragma unroll
        for (int tj = 0; tj < 4; tj++)
            b[tj] = __ldg(&Wfh[(ks * 16 + nb + tj) * 32 + lane]);
        unsigned a[2][4];
#pragma unroll
        for (int ti = 0; ti < 2; ti++) {
            const __half* ap = &sA[(mBase + ti * 16 + r) * 136 + ks * 16 + c * 2];
            a[ti][0] = *(const unsigned*)ap;
            a[ti][1] = *(const unsigned*)(ap + 8 * 136);
            a[ti][2] = *(const unsigned*)(ap + 8);
            a[ti][3] = *(const unsigned*)(ap + 8 * 136 + 8);
        }
#pragma unroll
        for (int ti = 0; ti < 2; ti++)
#pragma unroll
            for (int tj = 0; tj < 4; tj++)
                mma_f16(acc[ti][tj], a[ti], b[tj].x, b[tj].y);
    }
}

static const int SMEM_NODE = 64 * 136 * 2;      // 17408 B (x tile)
static const int SMEM_EDGE = 64 * 136 * 2 * 2;  // 34816 B (e tile + Ce tile)

// ---------------- kernel 0: zero num/den (fp16) + detect edge_index dtype ----------------
__global__ void zero_detect_kernel(const unsigned* __restrict__ w) {
    const size_t i = (size_t)blockIdx.x * 256 + threadIdx.x;
    float4 z = make_float4(0.f, 0.f, 0.f, 0.f);
    ((float4*)g_numh)[i] = z;
    ((float4*)g_denh)[i] = z;
    if (blockIdx.x == 0 && threadIdx.x < 32) {
        unsigned acc = 0;
        for (int k = threadIdx.x; k < 1024; k += 32) acc |= w[2 * k + 1];
#pragma unroll
        for (int o = 16; o; o >>= 1) acc |= __shfl_xor_sync(0xffffffffu, acc, o);
        if (threadIdx.x == 0) g_i64 = (acc == 0) ? 1 : 0;
    }
}

// ---------------- kernel 1: pack weights into fp16 fragment layout (m16n8k16 B) ----------------
__global__ void prep_kernel(const float* __restrict__ W0, const float* __restrict__ W1,
                            const float* __restrict__ W2, const float* __restrict__ W3,
                            const float* __restrict__ W4) {
    const float* Ws[5] = {W0, W1, W2, W3, W4};
    const int lane = threadIdx.x;
    const int g = blockIdx.x;      // ks*16+ng, ks in [0,8)
    const int mat = blockIdx.y;
    const float* W = Ws[mat];
    const int n = (g & 15) * 8 + (lane >> 2);
    const int k0 = (g >> 4) * 16 + (lane & 3) * 2;
    uint2 v;
    v.x = h2u(__floats2half2_rn(W[n * DIM + k0],     W[n * DIM + k0 + 1]));
    v.y = h2u(__floats2half2_rn(W[n * DIM + k0 + 8], W[n * DIM + k0 + 9]));
    g_Wfh[mat][g * 32 + lane] = v;
}

// ---------------- kernel 2: node GEMMs, one j per block ----------------
__global__ void __launch_bounds__(256, 4) node_gemm_kernel(
    const float* __restrict__ x,
    const float* __restrict__ b0, const float* __restrict__ b1,
    const float* __restrict__ b2, const float* __restrict__ b3) {
    extern __shared__ __half smemh[];
    __half* sX = smemh;  // [64][136] fp16 x tile

    const int tid = threadIdx.x;
    const int m0 = blockIdx.x * 64;
    const int j = blockIdx.y;

    const float* bias = (j == 0) ? b0 : (j == 1) ? b1 : (j == 2) ? b2 : b3;
    const uint2* Wfh = g_Wfh[j];

    for (int i = tid; i < 64 * 32; i += 256) {
        int row = i >> 5, c4 = (i & 31) << 2;
        float4 v = make_float4(0.f, 0.f, 0.f, 0.f);
        if (m0 + row < NN) v = *(const float4*)&x[(size_t)(m0 + row) * DIM + c4];
        uint2 u;
        u.x = h2u(__floats2half2_rn(v.x, v.y));
        u.y = h2u(__floats2half2_rn(v.z, v.w));
        *(uint2*)&sX[row * 136 + c4] = u;
    }
    __syncthreads();

    const int lane = tid & 31, wid = tid >> 5;
    const int r = lane >> 2, c = lane & 3;
    const int mBase = (wid & 1) * 32;
    const int nBase = (wid >> 1) * 32;
    const int nb = (wid >> 1) * 4;

    float acc[2][4][4];
#pragma unroll
    for (int tj = 0; tj < 4; tj++) {
        int n0 = nBase + tj * 8 + c * 2;
        float bv0 = __ldg(&bias[n0]), bv1 = __ldg(&bias[n0 + 1]);
#pragma unroll
        for (int ti = 0; ti < 2; ti++) {
            acc[ti][tj][0] = bv0; acc[ti][tj][1] = bv1;
            acc[ti][tj][2] = bv0; acc[ti][tj][3] = bv1;
        }
    }

    gemm_tile_h(sX, Wfh, acc, mBase, nb, r, c, lane);

    __half* outH = (j == 1) ? g_Bh : (j == 2) ? g_Dh : g_Eh;
#pragma unroll
    for (int ti = 0; ti < 2; ti++) {
#pragma unroll
        for (int half_i = 0; half_i < 2; half_i++) {
            const int m = m0 + mBase + ti * 16 + r + half_i * 8;
            if (m >= NN) continue;
#pragma unroll
            for (int tj = 0; tj < 4; tj++) {
                const int n0 = nBase + tj * 8 + c * 2;
                const float v0 = acc[ti][tj][half_i * 2];
                const float v1 = acc[ti][tj][half_i * 2 + 1];
                if (j == 0) {
                    *(float2*)&g_Ax[(size_t)m * DIM + n0] = make_float2(v0, v1);
                } else {
                    *(__half2*)&outH[(size_t)m * DIM + n0] = __floats2half2_rn(v0, v1);
                }
            }
        }
    }
}

// ---------------- kernel 3: fused edge kernel, fp16 GEMM ----------------
// e staged ONCE as fp16 (GEMM A + residual). Gathers use L2 evict-last policy to
// stay resident against the .cs e/e_out streams. Half2 epilogue, fp16 reds.
__global__ void __launch_bounds__(256, 4) edge_kernel(
    const float* __restrict__ e,
    const float* __restrict__ Cb,
    const void* __restrict__ eidx,
    const float* __restrict__ beg, const float* __restrict__ beb,
    const float* __restrict__ bem, const float* __restrict__ bev,
    float* __restrict__ e_out) {
    extern __shared__ __half smemh[];
    __half* sEh = smemh;               // [64][136] fp16 e tile (GEMM A + residual)
    __half* sCe = smemh + 64 * 136;    // [64][136] fp16 Ce tile

    const int tid = threadIdx.x;
    const size_t eBase = (size_t)blockIdx.x * 64;
    const uint2* Wfh = g_Wfh[4];

    for (int i = tid; i < 64 * 32; i += 256) {
        int row = i >> 5, c4 = (i & 31) << 2;
        float4 v;
        asm volatile("ld.global.cs.v4.f32 {%0,%1,%2,%3}, [%4];"
                     : "=f"(v.x), "=f"(v.y), "=f"(v.z), "=f"(v.w)
                     : "l"(&e[(eBase + row) * DIM + c4]));
        uint2 u;
        u.x = h2u(__floats2half2_rn(v.x, v.y));
        u.y = h2u(__floats2half2_rn(v.z, v.w));
        *(uint2*)&sEh[row * 136 + c4] = u;
    }
    __syncthreads();

    const int lane = tid & 31, wid = tid >> 5;
    const int r = lane >> 2, c = lane & 3;
    const int mBase = (wid & 1) * 32;
    const int nBase = (wid >> 1) * 32;
    const int nb = (wid >> 1) * 4;

    float acc[2][4][4];
#pragma unroll
    for (int tj = 0; tj < 4; tj++) {
        int n0 = nBase + tj * 8 + c * 2;
        float bv0 = __ldg(&Cb[n0]), bv1 = __ldg(&Cb[n0 + 1]);
#pragma unroll
        for (int ti = 0; ti < 2; ti++) {
            acc[ti][tj][0] = bv0; acc[ti][tj][1] = bv1;
            acc[ti][tj][2] = bv0; acc[ti][tj][3] = bv1;
        }
    }

    gemm_tile_h(sEh, Wfh, acc, mBase, nb, r, c, lane);

#pragma unroll
    for (int ti = 0; ti < 2; ti++) {
        int m = mBase + ti * 16 + r;
#pragma unroll
        for (int tj = 0; tj < 4; tj++) {
            int n0 = nBase + tj * 8 + c * 2;
            *(__half2*)&sCe[m * 136 + n0] =
                __floats2half2_rn(acc[ti][tj][0], acc[ti][tj][1]);
            *(__half2*)&sCe[(m + 8) * 136 + n0] =
                __floats2half2_rn(acc[ti][tj][2], acc[ti][tj][3]);
        }
    }
    __syncthreads();

    // ---- epilogue: warp w handles edges w*8..w*8+7, lane owns cols 4*lane..+3
    const int n = lane * 4;
    const uint64_t pol = make_evict_last_policy();
    const float4 gm = *(const float4*)&beg[n];
    const float4 bt = *(const float4*)&beb[n];
    const float4 mn = *(const float4*)&bem[n];
    const float4 vr = *(const float4*)&bev[n];
    const float s0c = gm.x * rsqrtf(vr.x + 1e-5f);
    const float s1c = gm.y * rsqrtf(vr.y + 1e-5f);
    const float s2c = gm.z * rsqrtf(vr.z + 1e-5f);
    const float s3c = gm.w * rsqrtf(vr.w + 1e-5f);
    const __half2 sH01 = __floats2half2_rn(s0c, s1c);
    const __half2 sH23 = __floats2half2_rn(s2c, s3c);
    const __half2 hH01 = __floats2half2_rn(bt.x - mn.x * s0c, bt.y - mn.y * s1c);
    const __half2 hH23 = __floats2half2_rn(bt.z - mn.z * s2c, bt.w - mn.w * s3c);
    const __half2 halfC = __floats2half2_rn(0.5f, 0.5f);
    const __half2 zeroC = __floats2half2_rn(0.f, 0.f);

    const int flag = g_i64;
    const long long* i64p = (const long long*)eidx;
    const int* i32p = (const int*)eidx;

    int srcs[8], dsts[8];
    if (flag) {
#pragma unroll
        for (int mi = 0; mi < 8; mi++) {
            const size_t ge = eBase + wid * 8 + mi;
            srcs[mi] = (int)__ldg(&i64p[ge]);
            dsts[mi] = (int)__ldg(&i64p[NE + ge]);
        }
    } else {
#pragma unroll
        for (int mi = 0; mi < 8; mi++) {
            const size_t ge = eBase + wid * 8 + mi;
            srcs[mi] = __ldg(&i32p[ge]);
            dsts[mi] = __ldg(&i32p[NE + ge]);
        }
    }

#pragma unroll
    for (int mi = 0; mi < 8; mi++) {
        const int m = wid * 8 + mi;
        const size_t ge = eBase + m;
        const int srcI = srcs[mi], dstI = dsts[mi];

        const uint2 exu = ldg_el_u2(&g_Eh[(size_t)srcI * DIM + n], pol);
        const uint2 bxu = ldg_el_u2(&g_Bh[(size_t)srcI * DIM + n], pol);
        const uint2 dhu = ldg_el_u2(&g_Dh[(size_t)dstI * DIM + n], pol);
        const uint2 ceu = *(const uint2*)&sCe[m * 136 + n];
        const uint2 ru  = *(const uint2*)&sEh[m * 136 + n];

        const __half2 ex01 = *(const __half2*)&exu.x;
        const __half2 ex23 = *(const __half2*)&exu.y;
        const __half2 bx01 = *(const __half2*)&bxu.x;
        const __half2 bx23 = *(const __half2*)&bxu.y;
        const __half2 d01  = *(const __half2*)&dhu.x;
        const __half2 d23  = *(const __half2*)&dhu.y;
        const __half2 ce01 = *(const __half2*)&ceu.x;
        const __half2 ce23 = *(const __half2*)&ceu.y;

        const __half2 eij01 = __hadd2(__hadd2(ce01, d01), ex01);
        const __half2 eij23 = __hadd2(__hadd2(ce23, d23), ex23);

        const __half2 sg01 = __hfma2(tanh_h2(__hmul2(eij01, halfC)), halfC, halfC);
        const __half2 sg23 = __hfma2(tanh_h2(__hmul2(eij23, halfC)), halfC, halfC);

        const __half2 nu01 = __hmul2(sg01, bx01);
        const __half2 nu23 = __hmul2(sg23, bx23);

        __half* np = &g_numh[(size_t)dstI * DIM + n];
        asm volatile("red.global.add.noftz.v2.f16x2 [%0], {%1,%2};"
                     :: "l"(np), "r"(h2u(nu01)), "r"(h2u(nu23)) : "memory");
        __half* dp = &g_denh[(size_t)dstI * DIM + n];
        asm volatile("red.global.add.noftz.v2.f16x2 [%0], {%1,%2};"
                     :: "l"(dp), "r"(h2u(sg01)), "r"(h2u(sg23)) : "memory");

        const __half2 bn01 = __hmax2(__hfma2(eij01, sH01, hH01), zeroC);
        const __half2 bn23 = __hmax2(__hfma2(eij23, sH23, hH23), zeroC);
        const float2 rb01 = __half22float2(bn01);
        const float2 rb23 = __half22float2(bn23);
        const float2 r01 = __half22float2(*(const __half2*)&ru.x);
        const float2 r23 = __half22float2(*(const __half2*)&ru.y);

        float4 o;
        o.x = r01.x + rb01.x;
        o.y = r01.y + rb01.y;
        o.z = r23.x + rb23.x;
        o.w = r23.y + rb23.y;
        asm volatile("st.global.cs.v4.f32 [%0], {%1,%2,%3,%4};"
                     :: "l"(&e_out[ge * DIM + n]),
                        "f"(o.x), "f"(o.y), "f"(o.z), "f"(o.w)
                     : "memory");
    }
}

// ---------------- kernel 4: node update ----------------
__global__ void update_kernel(const float* __restrict__ x,
                              const float* __restrict__ bxg, const float* __restrict__ bxb,
                              const float* __restrict__ bxm, const float* __restrict__ bxv,
                              float* __restrict__ x_out) {
    const size_t i = (size_t)blockIdx.x * 256 + threadIdx.x;
    const int c4 = ((int)i & 31) << 2;

    const uint2 nuu = ((const uint2*)g_numh)[i];
    const uint2 deu = ((const uint2*)g_denh)[i];
    const float2 nu01 = __half22float2(*(const __half2*)&nuu.x);
    const float2 nu23 = __half22float2(*(const __half2*)&nuu.y);
    const float2 de01 = __half22float2(*(const __half2*)&deu.x);
    const float2 de23 = __half22float2(*(const __half2*)&deu.y);

    const float4 ax = ((const float4*)g_Ax)[i];
    const float4 xv = ((const float4*)x)[i];

    const float4 gm = *(const float4*)&bxg[c4];
    const float4 bt = *(const float4*)&bxb[c4];
    const float4 mn = *(const float4*)&bxm[c4];
    const float4 vr = *(const float4*)&bxv[c4];

    const float s0 = gm.x * rsqrtf(vr.x + 1e-5f);
    const float s1 = gm.y * rsqrtf(vr.y + 1e-5f);
    const float s2 = gm.z * rsqrtf(vr.z + 1e-5f);
    const float s3 = gm.w * rsqrtf(vr.w + 1e-5f);
    const float h0 = bt.x - mn.x * s0;
    const float h1 = bt.y - mn.y * s1;
    const float h2 = bt.z - mn.z * s2;
    const float h3 = bt.w - mn.w * s3;

    const float v0 = ax.x + nu01.x / (de01.x + 1e-6f);
    const float v1 = ax.y + nu01.y / (de01.y + 1e-6f);
    const float v2 = ax.z + nu23.x / (de23.x + 1e-6f);
    const float v3 = ax.w + nu23.y / (de23.y + 1e-6f);

    float4 o;
    o.x = xv.x + fmaxf(0.f, v0 * s0 + h0);
    o.y = xv.y + fmaxf(0.f, v1 * s1 + h1);
    o.z = xv.z + fmaxf(0.f, v2 * s2 + h2);
    o.w = xv.w + fmaxf(0.f, v3 * s3 + h3);
    asm volatile("st.global.cs.v4.f32 [%0], {%1,%2,%3,%4};"
                 :: "l"(&((float4*)x_out)[i]),
                    "f"(o.x), "f"(o.y), "f"(o.z), "f"(o.w)
                 : "memory");
}

// ---------------- launch ----------------
extern "C" void kernel_launch(void* const* d_in, const int* in_sizes, int n_in,
                              void* d_out, int out_size) {
    const float* x  = (const float*)d_in[0];
    const float* e  = (const float*)d_in[1];
    const float* Aw = (const float*)d_in[2];
    const float* Ab = (const float*)d_in[3];
    const float* Bw = (const float*)d_in[4];
    const float* Bb = (const float*)d_in[5];
    const float* Cw = (const float*)d_in[6];
    const float* Cb = (const float*)d_in[7];
    const float* Dw = (const float*)d_in[8];
    const float* Db = (const float*)d_in[9];
    const float* Ew = (const float*)d_in[10];
    const float* Eb = (const float*)d_in[11];
    const float* bxg = (const float*)d_in[12];
    const float* bxb = (const float*)d_in[13];
    const float* bxm = (const float*)d_in[14];
    const float* bxv = (const float*)d_in[15];
    const float* beg = (const float*)d_in[16];
    const float* beb = (const float*)d_in[17];
    const float* bem = (const float*)d_in[18];
    const float* bev = (const float*)d_in[19];
    const void*  eidx = d_in[20];

    float* x_out = (float*)d_out;
    float* e_out = x_out + (size_t)NN * DIM;

    zero_detect_kernel<<<3125, 256>>>((const unsigned*)eidx);
    // weight order: 0:A 1:B 2:D 3:E 4:C  (fp16 fragments, 8 k-steps)
    prep_kernel<<<dim3(128, 5), 32>>>(Aw, Bw, Dw, Ew, Cw);
    node_gemm_kernel<<<dim3(782, 4), 256, SMEM_NODE>>>(x, Ab, Bb, Db, Eb);
    edge_kernel<<<10000, 256, SMEM_EDGE>>>(e, Cb, eidx, beg, beb, bem, bev, e_out);
    update_kernel<<<6250, 256>>>(x, bxg, bxb, bxm, bxv, x_out);
}